// round 13
// baseline (speedup 1.0000x reference)
#include <cuda_runtime.h>
#include <cuda_fp16.h>
#include <cstdint>

#define NTB 10
__device__ float g_P1[4][64 * 256];
__device__ float g_P2[8][64 * 512];
__device__ float g_P3[8][64 * 1024];
__device__ uint32_t g_WHi[64 * 512];
__device__ uint32_t g_WLo[64 * 512];
__device__ float g_Cpart[NTB][64][4096];
__device__ float g_rsumP[NTB][4096];

__device__ __forceinline__ uint32_t smem_u32(const void* p) {
    uint32_t a;
    asm("{ .reg .u64 t; cvta.to.shared.u64 t, %1; cvt.u32.u64 %0, t; }" : "=r"(a) : "l"(p));
    return a;
}
__device__ __forceinline__ uint32_t cvt2h(float lo, float hi) {
    uint32_t r;
    asm("cvt.rn.f16x2.f32 %0, %1, %2;" : "=r"(r) : "f"(hi), "f"(lo));
    return r;
}
__device__ __forceinline__ uint32_t hpack(__half a, __half b) {
    return (uint32_t)__half_as_ushort(a) | ((uint32_t)__half_as_ushort(b) << 16);
}
__device__ __forceinline__ void hsplit2(float v0, float v1, uint32_t& hi, uint32_t& lo) {
    __half h0 = __float2half(v0), h1 = __float2half(v1);
    hi = hpack(h0, h1);
    lo = hpack(__float2half(v0 - __half2float(h0)), __float2half(v1 - __half2float(h1)));
}
__device__ __forceinline__ void ldmA(uint32_t* r, uint32_t a) {
    asm volatile("ldmatrix.sync.aligned.m8n8.x4.shared.b16 {%0,%1,%2,%3}, [%4];"
                 : "=r"(r[0]), "=r"(r[1]), "=r"(r[2]), "=r"(r[3]) : "r"(a));
}
__device__ __forceinline__ void ldmBT(uint32_t* r, uint32_t a) {
    asm volatile("ldmatrix.sync.aligned.m8n8.x4.trans.shared.b16 {%0,%1,%2,%3}, [%4];"
                 : "=r"(r[0]), "=r"(r[1]), "=r"(r[2]), "=r"(r[3]) : "r"(a));
}
__device__ __forceinline__ void mma(float* c, const uint32_t a[4], uint32_t b0, uint32_t b1) {
    asm volatile("mma.sync.aligned.m16n8k16.row.col.f32.f16.f16.f32 "
                 "{%0,%1,%2,%3},{%4,%5,%6,%7},{%8,%9},{%0,%1,%2,%3};"
                 : "+f"(c[0]), "+f"(c[1]), "+f"(c[2]), "+f"(c[3])
                 : "r"(a[0]), "r"(a[1]), "r"(a[2]), "r"(a[3]), "r"(b0), "r"(b1));
}

// P1[ks][i,j] = sum_{k in slice} W4[k,i]*W3[j,k].  grid(4 n, 4 ksplit)
__global__ __launch_bounds__(256) void k_fold1(const float* __restrict__ W4,
                                               const float* __restrict__ W3) {
    __shared__ float As[64][33], Bs[64][33];
    int n0 = blockIdx.x * 64, k0 = blockIdx.y * 32;
    int tid = threadIdx.x, tr = tid >> 4, tc = tid & 15;
    float acc[4][4] = {};
#pragma unroll
    for (int i = 0; i < 8; i++) {
        int lin = tid + 256 * i, m = lin >> 5, k = lin & 31;
        As[m][k] = W4[(k0 + k) * 64 + m];
        Bs[m][k] = W3[(n0 + m) * 128 + k0 + k];
    }
    __syncthreads();
#pragma unroll 4
    for (int kk = 0; kk < 32; kk++) {
        float a[4], b[4];
#pragma unroll
        for (int r = 0; r < 4; r++) a[r] = As[4 * tr + r][kk];
#pragma unroll
        for (int c = 0; c < 4; c++) b[c] = Bs[4 * tc + c][kk];
#pragma unroll
        for (int r = 0; r < 4; r++)
#pragma unroll
            for (int c = 0; c < 4; c++) acc[r][c] += a[r] * b[c];
    }
#pragma unroll
    for (int r = 0; r < 4; r++)
#pragma unroll
        for (int c = 0; c < 4; c++)
            g_P1[blockIdx.y][(4 * tr + r) * 256 + n0 + 4 * tc + c] = acc[r][c];
}

// NT GEMM, K-split; A = sum of np partials (each 64*Ktot). grid(N/64, Ktot/Kslice)
__global__ __launch_bounds__(256) void k_ntk(const float* __restrict__ A, int np,
                                             const float* __restrict__ Bm,
                                             float* __restrict__ Cout,
                                             int Ktot, int Kslice, int N) {
    __shared__ float As[64][33], Bs[64][33];
    int n0 = blockIdx.x * 64, koff = blockIdx.y * Kslice;
    float* C = Cout + (size_t)blockIdx.y * 64 * N;
    int tid = threadIdx.x, tr = tid >> 4, tc = tid & 15;
    float acc[4][4] = {};
    for (int k0 = koff; k0 < koff + Kslice; k0 += 32) {
#pragma unroll
        for (int i = 0; i < 8; i++) {
            int lin = tid + 256 * i, m = lin >> 5, k = lin & 31;
            float a = 0.f;
            for (int p = 0; p < np; p++) a += A[(size_t)p * 64 * Ktot + m * Ktot + k0 + k];
            As[m][k] = a;
            Bs[m][k] = Bm[(n0 + m) * Ktot + k0 + k];
        }
        __syncthreads();
#pragma unroll 4
        for (int kk = 0; kk < 32; kk++) {
            float a[4], b[4];
#pragma unroll
            for (int r = 0; r < 4; r++) a[r] = As[4 * tr + r][kk];
#pragma unroll
            for (int c = 0; c < 4; c++) b[c] = Bs[4 * tc + c][kk];
#pragma unroll
            for (int r = 0; r < 4; r++)
#pragma unroll
                for (int c = 0; c < 4; c++) acc[r][c] += a[r] * b[c];
        }
        __syncthreads();
    }
#pragma unroll
    for (int r = 0; r < 4; r++)
#pragma unroll
        for (int c = 0; c < 4; c++)
            C[(4 * tr + r) * N + n0 + 4 * tc + c] = acc[r][c];
}

// Sum 8 Wt partials -> fp16 hi/lo packed pairs.
__global__ void k_cvt() {
    int i = blockIdx.x * blockDim.x + threadIdx.x;   // pair index < 32768
    float w0 = 0.f, w1 = 0.f;
#pragma unroll
    for (int p = 0; p < 8; p++) {
        w0 += g_P3[p][2 * i];
        w1 += g_P3[p][2 * i + 1];
    }
    uint32_t hi, lo;
    hsplit2(w0, w1, hi, lo);
    g_WHi[i] = hi;
    g_WLo[i] = lo;
}

// Projection + fused cov partials. grid(NTB,64), 256 thr, dyn smem 71680.
__global__ __launch_bounds__(256, 2) void k_proj_cov(const float* __restrict__ x) {
    extern __shared__ __align__(16) unsigned char sm[];
    const int OW0 = 0, OW1 = 18432, OX0 = 36864, OX1 = 54272;
    __shared__ float rs[2][64];
    int tid = threadIdx.x, w = tid >> 5, lane = tid & 31;
    int b = blockIdx.y, t0 = blockIdx.x * 128;
    uint32_t sb = smem_u32(sm);
    const float* xb = x + (size_t)b * 1024 * 1200;
    int wr = (w >> 1) * 16, wc = (w & 1) * 64;
    int g = lane >> 2, tq = lane & 3;
    int arow = wr + (lane & 15), asel = 8 * (lane >> 4);
    int wm = tid >> 2, wq = 8 * (tid & 3);
    float acc[8][4] = {};

    for (int pc = 0; pc <= 16; pc++) {
        uint4 wh0, wh1, wl0, wl1;
        float4 xv[8];
        if (pc < 16) {
            const uint4* pH = (const uint4*)&g_WHi[wm * 512 + pc * 32 + wq];
            const uint4* pL = (const uint4*)&g_WLo[wm * 512 + pc * 32 + wq];
            wh0 = pH[0]; wh1 = pH[1]; wl0 = pL[0]; wl1 = pL[1];
#pragma unroll
            for (int i = 0; i < 8; i++) {
                int lin = tid + 256 * i, k = lin >> 5, tt = t0 + 4 * (lin & 31);
                xv[i] = (tt < 1200) ? *(const float4*)(xb + (size_t)(pc * 64 + k) * 1200 + tt)
                                    : make_float4(0.f, 0.f, 0.f, 0.f);
            }
        }
        if (pc > 0) {
            uint32_t wb = sb + (((pc - 1) & 1) ? OW1 : OW0);
            uint32_t xba = sb + (((pc - 1) & 1) ? OX1 : OX0);
#pragma unroll
            for (int ks = 0; ks < 4; ks++) {
                int kk = 16 * ks;
                uint32_t ah[4], al[4];
                uint32_t aa = wb + arow * 144 + (kk + asel) * 2;
                ldmA(ah, aa);
                ldmA(al, aa + 9216);
#pragma unroll
                for (int nb = 0; nb < 4; nb++) {
                    uint32_t r[4];
                    ldmBT(r, xba + (kk + (lane & 15)) * 272 + (wc + 16 * nb + asel) * 2);
                    mma(acc[2 * nb],     ah, r[0], r[1]);
                    mma(acc[2 * nb],     al, r[0], r[1]);
                    mma(acc[2 * nb + 1], ah, r[2], r[3]);
                    mma(acc[2 * nb + 1], al, r[2], r[3]);
                }
            }
        }
        if (pc < 16) {
            unsigned char* dW = sm + ((pc & 1) ? OW1 : OW0) + wm * 144 + wq * 4;
            *(uint4*)dW = wh0; *(uint4*)(dW + 16) = wh1;
            *(uint4*)(dW + 9216) = wl0; *(uint4*)(dW + 9216 + 16) = wl1;
            unsigned char* dX = sm + ((pc & 1) ? OX1 : OX0);
#pragma unroll
            for (int i = 0; i < 8; i++) {
                int lin = tid + 256 * i, k = lin >> 5, t4 = lin & 31;
                uint2 p;
                p.x = cvt2h(xv[i].x, xv[i].y);
                p.y = cvt2h(xv[i].z, xv[i].w);
                *(uint2*)(dX + k * 272 + 8 * t4) = p;
            }
        }
        __syncthreads();
    }

    {
        float s0 = 0.f, s1 = 0.f;
#pragma unroll
        for (int nf = 0; nf < 8; nf++) {
            s0 += acc[nf][0] + acc[nf][1];
            s1 += acc[nf][2] + acc[nf][3];
        }
        s0 += __shfl_xor_sync(0xffffffffu, s0, 1);
        s0 += __shfl_xor_sync(0xffffffffu, s0, 2);
        s1 += __shfl_xor_sync(0xffffffffu, s1, 1);
        s1 += __shfl_xor_sync(0xffffffffu, s1, 2);
        if (tq == 0) { rs[w & 1][wr + g] = s0; rs[w & 1][wr + g + 8] = s1; }
    }
    unsigned char* Yh = sm + OX0;
    unsigned char* Yl = sm + OX1;
#pragma unroll
    for (int nf = 0; nf < 8; nf++) {
        int c0 = wc + 8 * nf + 2 * tq;
        uint32_t h, l;
        hsplit2(acc[nf][0], acc[nf][1], h, l);
        *(uint32_t*)(Yh + (wr + g) * 272 + c0 * 2) = h;
        *(uint32_t*)(Yl + (wr + g) * 272 + c0 * 2) = l;
        hsplit2(acc[nf][2], acc[nf][3], h, l);
        *(uint32_t*)(Yh + (wr + g + 8) * 272 + c0 * 2) = h;
        *(uint32_t*)(Yl + (wr + g + 8) * 272 + c0 * 2) = l;
    }
    __syncthreads();
    if (tid < 64) g_rsumP[blockIdx.x][b * 64 + tid] = rs[0][tid] + rs[1][tid];

    {
        int cr = (w & 3) * 16, cn = (w >> 2) * 32;
        float cc[4][4] = {};
        uint32_t yh = sb + OX0, yl = sb + OX1;
#pragma unroll
        for (int kk = 0; kk < 128; kk += 16) {
            uint32_t ah[4], al[4], bh[8], bl[8];
            uint32_t aa = (cr + (lane & 15)) * 272 + (kk + asel) * 2;
            ldmA(ah, yh + aa); ldmA(al, yl + aa);
            uint32_t ba = (cn + (lane & 15)) * 272 + (kk + asel) * 2;
            ldmA(bh, yh + ba); ldmA(bh + 4, yh + ba + 16 * 272);
            ldmA(bl, yl + ba); ldmA(bl + 4, yl + ba + 16 * 272);
#pragma unroll
            for (int jb = 0; jb < 4; jb++) {
                int base = (jb >> 1) * 4 + (jb & 1);
                uint32_t b0h = bh[base], b1h = bh[base + 2];
                uint32_t b0l = bl[base], b1l = bl[base + 2];
                mma(cc[jb], ah, b0h, b1h);
                mma(cc[jb], ah, b0l, b1l);
                mma(cc[jb], al, b0h, b1h);
            }
        }
        float* Cp = g_Cpart[blockIdx.x][b];
#pragma unroll
        for (int jb = 0; jb < 4; jb++) {
            int col = cn + 8 * jb + 2 * tq;
            *(float2*)&Cp[(cr + g) * 64 + col]     = make_float2(cc[jb][0], cc[jb][1]);
            *(float2*)&Cp[(cr + g + 8) * 64 + col] = make_float2(cc[jb][2], cc[jb][3]);
        }
    }
}

// tensor 64x64 step on fp16 hi/lo pairs: D = s*(A@B) + dg*I.
// out32: write fp32 [64][64] to oD instead of hi/lo pairs.
__device__ __noinline__ void mm64t(unsigned char* sm, uint32_t sb, int oA, int oB, int oD,
                                   float s, float dg, int tid, int out32) {
    int w = tid >> 5, lane = tid & 31, g = lane >> 2, tq = lane & 3;
    int cr = (w & 3) * 16, cn = (w >> 2) * 32;
    int lr = lane & 15, ls = 8 * (lane >> 4);
    float acc[4][4] = {};
#pragma unroll
    for (int kk = 0; kk < 64; kk += 16) {
        uint32_t ah[4], al[4], bh[8], bl[8];
        uint32_t aa = sb + oA + (cr + lr) * 144 + (kk + ls) * 2;
        ldmA(ah, aa); ldmA(al, aa + 9216);
        uint32_t ba = sb + oB + (kk + lr) * 144 + (cn + ls) * 2;
        ldmBT(bh, ba); ldmBT(bh + 4, ba + 32);
        ldmBT(bl, ba + 9216); ldmBT(bl + 4, ba + 9216 + 32);
#pragma unroll
        for (int jb = 0; jb < 4; jb++) {
            int base = (jb >> 1) * 4 + (jb & 1) * 2;
            mma(acc[jb], ah, bh[base], bh[base + 1]);
            mma(acc[jb], ah, bl[base], bl[base + 1]);
            mma(acc[jb], al, bh[base], bh[base + 1]);
        }
    }
    if (out32) {
        float* Df = (float*)(sm + oD);
#pragma unroll
        for (int jb = 0; jb < 4; jb++) {
            int col = cn + 8 * jb + 2 * tq;
#pragma unroll
            for (int h2 = 0; h2 < 2; h2++) {
                int row = cr + g + 8 * h2;
                float v0 = s * acc[jb][2 * h2]     + ((row == col) ? dg : 0.f);
                float v1 = s * acc[jb][2 * h2 + 1] + ((row == col + 1) ? dg : 0.f);
                *(float2*)&Df[row * 64 + col] = make_float2(v0, v1);
            }
        }
    } else {
        __half* Dh = (__half*)(sm + oD);
        __half* Dl = (__half*)(sm + oD + 9216);
#pragma unroll
        for (int jb = 0; jb < 4; jb++) {
            int col = cn + 8 * jb + 2 * tq;
#pragma unroll
            for (int h2 = 0; h2 < 2; h2++) {
                int row = cr + g + 8 * h2;
                float v0 = s * acc[jb][2 * h2]     + ((row == col) ? dg : 0.f);
                float v1 = s * acc[jb][2 * h2 + 1] + ((row == col + 1) ? dg : 0.f);
                uint32_t hi, lo;
                hsplit2(v0, v1, hi, lo);
                *(uint32_t*)(Dh + row * 72 + col) = hi;
                *(uint32_t*)(Dl + row * 72 + col) = lo;
            }
        }
    }
    __syncthreads();
}

// Fused reduce + center + logm + linear head. One block per batch matrix.
__global__ __launch_bounds__(256) void k_logm(const float* __restrict__ lw,
                                              const float* __restrict__ lb,
                                              float* __restrict__ out) {
    extern __shared__ __align__(16) unsigned char sm[];
    __shared__ float s_r[64], red[64];
    __shared__ float s_inva, s_lna;
    int b = blockIdx.x, tid = threadIdx.x, w = tid >> 5, lane = tid & 31;
    uint32_t sb = smem_u32(sm);
    const float iT = 1.f / 1200.f, iT1 = 1.f / 1199.f;

    if (tid < 64) {
        float v = 0.f;
#pragma unroll
        for (int p = 0; p < NTB; p++) v += g_rsumP[p][b * 64 + tid];
        s_r[tid] = v;
    }
    __syncthreads();
    if (tid < 64) {
        float d = 0.f;
#pragma unroll
        for (int p = 0; p < NTB; p++) d += g_Cpart[p][b][tid * 65];
        red[tid] = (d - s_r[tid] * s_r[tid] * iT) * iT1;
    }
    __syncthreads();
    if (tid == 0) {
        float tr = 0.f;
        for (int i = 0; i < 64; i++) tr += red[i];
        float al = tr * (1.f / 64.f);
        s_inva = 1.f / al; s_lna = logf(al);
    }
    __syncthreads();
    float inva = s_inva;

    int oY = 0, oZ = 18432, oT = 36864, oU = 55296;
#pragma unroll
    for (int i = 0; i < 16; i++) {
        int lin = tid + 256 * i, r = lin >> 6, c = lin & 63;
        float v = 0.f;
#pragma unroll
        for (int p = 0; p < NTB; p++) v += g_Cpart[p][b][lin];
        float a = (v - s_r[r] * s_r[c] * iT) * iT1 * inva;
        __half h = __float2half(a);
        ((__half*)(sm + oY))[r * 72 + c] = h;
        ((__half*)(sm + oY + 9216))[r * 72 + c] = __float2half(a - __half2float(h));
        ((__half*)(sm + oZ))[r * 72 + c] = __float2half((r == c) ? 1.f : 0.f);
        ((__half*)(sm + oZ + 9216))[r * 72 + c] = __float2half(0.f);
    }
    __syncthreads();

    for (int it = 0; it < 5; it++) {
        mm64t(sm, sb, oZ, oY, oT, -1.f, 3.f, tid, 0);
        mm64t(sm, sb, oY, oT, oU, 0.5f, 0.f, tid, 0);
        mm64t(sm, sb, oT, oZ, oY, 0.5f, 0.f, tid, 0);
        int t = oY; oY = oU; oU = oT; oT = oZ; oZ = t;
    }
    __half *SH = (__half*)(sm + oY), *SL = (__half*)(sm + oY + 9216);
    __half *MH = (__half*)(sm + oZ), *ML = (__half*)(sm + oZ + 9216);
    __half *PH = (__half*)(sm + oT), *PL = (__half*)(sm + oT + 9216);
#pragma unroll
    for (int i = 0; i < 16; i++) {
        int lin = tid + 256 * i, r = lin >> 6, c = lin & 63;
        int idx = r * 72 + c;
        float m = __half2float(SH[idx]) + __half2float(SL[idx]) - ((r == c) ? 1.f : 0.f);
        __half mh = __float2half(m);
        MH[idx] = mh; ML[idx] = __float2half(m - __half2float(mh));
        float pv = (-1.f / 10.f) * m + ((r == c) ? (1.f / 9.f) : 0.f);
        __half ph = __float2half(pv);
        PH[idx] = ph; PL[idx] = __float2half(pv - __half2float(ph));
    }
    __syncthreads();
    int oP = oT, oQ = oU;
    for (int k = 8; k >= 1; k--) {
        float ck = ((k & 1) ? 1.f : -1.f) / (float)k;
        mm64t(sm, sb, oZ, oP, oQ, 1.f, ck, tid, 0);
        int t = oP; oP = oQ; oQ = t;
    }
    mm64t(sm, sb, oZ, oP, oQ, 2.f, s_lna, tid, 1);   // fp32 logC into oQ

    // linear head: out[b,j] = dot(logC, lw[j]) + lb[j]
    float* Qf = (float*)(sm + oQ);
    for (int j = w; j < 11; j += 8) {
        const float* wj = lw + (size_t)j * 4096;
        float s = 0.f;
        for (int i = lane * 4; i < 4096; i += 128) {
            float4 qv = *(float4*)&Qf[i];
            float4 wv = *(const float4*)&wj[i];
            s += qv.x * wv.x + qv.y * wv.y + qv.z * wv.z + qv.w * wv.w;
        }
#pragma unroll
        for (int o = 16; o > 0; o >>= 1) s += __shfl_xor_sync(0xffffffffu, s, o);
        if (lane == 0) out[b * 11 + j] = s + lb[j];
    }
}

extern "C" void kernel_launch(void* const* d_in, const int* in_sizes, int n_in,
                              void* d_out, int out_size) {
    const float* x  = (const float*)d_in[0];
    const float* W1 = (const float*)d_in[1];
    const float* W2 = (const float*)d_in[2];
    const float* W3 = (const float*)d_in[3];
    const float* W4 = (const float*)d_in[4];
    const float* lw = (const float*)d_in[5];
    const float* lb = (const float*)d_in[6];
    float* out = (float*)d_out;

    float *pP1, *pP2, *pP3;
    cudaGetSymbolAddress((void**)&pP1, g_P1);
    cudaGetSymbolAddress((void**)&pP2, g_P2);
    cudaGetSymbolAddress((void**)&pP3, g_P3);

    static bool done = false;
    if (!done) {
        cudaFuncSetAttribute(k_proj_cov, cudaFuncAttributeMaxDynamicSharedMemorySize, 71680);
        cudaFuncSetAttribute(k_logm, cudaFuncAttributeMaxDynamicSharedMemorySize, 73728);
        done = true;
    }
    k_fold1<<<dim3(4, 4), 256>>>(W4, W3);                          // P1[4] partials
    k_ntk<<<dim3(8, 8),  256>>>(pP1, 4, W2, pP2, 256, 32, 512);    // P2[8] partials
    k_ntk<<<dim3(16, 8), 256>>>(pP2, 8, W1, pP3, 512, 64, 1024);   // P3[8] partials
    k_cvt<<<128, 256>>>();                                         // -> fp16 hi/lo
    k_proj_cov<<<dim3(NTB, 64), 256, 71680>>>(x);
    k_logm<<<64, 256, 73728>>>(lw, lb, out);
}

// round 14
// speedup vs baseline: 1.6613x; 1.6613x over previous
#include <cuda_runtime.h>
#include <cuda_fp16.h>
#include <cstdint>

#define NTB 10
__device__ float g_P1[4][64 * 256];
__device__ float g_P2[8][64 * 512];
__device__ float g_P3[8][64 * 1024];
__device__ uint32_t g_WHi[64 * 512];
__device__ uint32_t g_WLo[64 * 512];
__device__ float g_Cpart[NTB][64][4096];
__device__ float g_rsumP[NTB][4096];

__device__ __forceinline__ uint32_t smem_u32(const void* p) {
    uint32_t a;
    asm("{ .reg .u64 t; cvta.to.shared.u64 t, %1; cvt.u32.u64 %0, t; }" : "=r"(a) : "l"(p));
    return a;
}
__device__ __forceinline__ uint32_t cvt2h(float lo, float hi) {
    uint32_t r;
    asm("cvt.rn.f16x2.f32 %0, %1, %2;" : "=r"(r) : "f"(hi), "f"(lo));
    return r;
}
__device__ __forceinline__ uint32_t hpack(__half a, __half b) {
    return (uint32_t)__half_as_ushort(a) | ((uint32_t)__half_as_ushort(b) << 16);
}
__device__ __forceinline__ void hsplit2(float v0, float v1, uint32_t& hi, uint32_t& lo) {
    __half h0 = __float2half(v0), h1 = __float2half(v1);
    hi = hpack(h0, h1);
    lo = hpack(__float2half(v0 - __half2float(h0)), __float2half(v1 - __half2float(h1)));
}
__device__ __forceinline__ void ldmA(uint32_t* r, uint32_t a) {
    asm volatile("ldmatrix.sync.aligned.m8n8.x4.shared.b16 {%0,%1,%2,%3}, [%4];"
                 : "=r"(r[0]), "=r"(r[1]), "=r"(r[2]), "=r"(r[3]) : "r"(a));
}
__device__ __forceinline__ void ldmBT(uint32_t* r, uint32_t a) {
    asm volatile("ldmatrix.sync.aligned.m8n8.x4.trans.shared.b16 {%0,%1,%2,%3}, [%4];"
                 : "=r"(r[0]), "=r"(r[1]), "=r"(r[2]), "=r"(r[3]) : "r"(a));
}
__device__ __forceinline__ void mma(float* c, const uint32_t a[4], uint32_t b0, uint32_t b1) {
    asm volatile("mma.sync.aligned.m16n8k16.row.col.f32.f16.f16.f32 "
                 "{%0,%1,%2,%3},{%4,%5,%6,%7},{%8,%9},{%0,%1,%2,%3};"
                 : "+f"(c[0]), "+f"(c[1]), "+f"(c[2]), "+f"(c[3])
                 : "r"(a[0]), "r"(a[1]), "r"(a[2]), "r"(a[3]), "r"(b0), "r"(b1));
}

// P1[ks][i,j] = sum_{k in slice} W4[k,i]*W3[j,k].  grid(4 n, 4 ksplit)
__global__ __launch_bounds__(256) void k_fold1(const float* __restrict__ W4,
                                               const float* __restrict__ W3) {
    __shared__ float As[64][33], Bs[64][33];
    int n0 = blockIdx.x * 64, k0 = blockIdx.y * 32;
    int tid = threadIdx.x, tr = tid >> 4, tc = tid & 15;
    float acc[4][4] = {};
#pragma unroll
    for (int i = 0; i < 8; i++) {
        int lin = tid + 256 * i, m = lin >> 5, k = lin & 31;
        As[m][k] = W4[(k0 + k) * 64 + m];
        Bs[m][k] = W3[(n0 + m) * 128 + k0 + k];
    }
    __syncthreads();
#pragma unroll 4
    for (int kk = 0; kk < 32; kk++) {
        float a[4], b[4];
#pragma unroll
        for (int r = 0; r < 4; r++) a[r] = As[4 * tr + r][kk];
#pragma unroll
        for (int c = 0; c < 4; c++) b[c] = Bs[4 * tc + c][kk];
#pragma unroll
        for (int r = 0; r < 4; r++)
#pragma unroll
            for (int c = 0; c < 4; c++) acc[r][c] += a[r] * b[c];
    }
#pragma unroll
    for (int r = 0; r < 4; r++)
#pragma unroll
        for (int c = 0; c < 4; c++)
            g_P1[blockIdx.y][(4 * tr + r) * 256 + n0 + 4 * tc + c] = acc[r][c];
}

// NT GEMM, K-split; A = sum of NP partials (compile-time -> unrolled, full MLP).
template <int NP>
__global__ __launch_bounds__(256) void k_ntk(const float* __restrict__ A,
                                             const float* __restrict__ Bm,
                                             float* __restrict__ Cout,
                                             int Ktot, int Kslice, int N) {
    __shared__ float As[64][33], Bs[64][33];
    int n0 = blockIdx.x * 64, koff = blockIdx.y * Kslice;
    float* C = Cout + (size_t)blockIdx.y * 64 * N;
    int tid = threadIdx.x, tr = tid >> 4, tc = tid & 15;
    float acc[4][4] = {};
    for (int k0 = koff; k0 < koff + Kslice; k0 += 32) {
#pragma unroll
        for (int i = 0; i < 8; i++) {
            int lin = tid + 256 * i, m = lin >> 5, k = lin & 31;
            float a = 0.f;
#pragma unroll
            for (int p = 0; p < NP; p++) a += A[(size_t)p * 64 * Ktot + m * Ktot + k0 + k];
            As[m][k] = a;
            Bs[m][k] = Bm[(n0 + m) * Ktot + k0 + k];
        }
        __syncthreads();
#pragma unroll 4
        for (int kk = 0; kk < 32; kk++) {
            float a[4], b[4];
#pragma unroll
            for (int r = 0; r < 4; r++) a[r] = As[4 * tr + r][kk];
#pragma unroll
            for (int c = 0; c < 4; c++) b[c] = Bs[4 * tc + c][kk];
#pragma unroll
            for (int r = 0; r < 4; r++)
#pragma unroll
                for (int c = 0; c < 4; c++) acc[r][c] += a[r] * b[c];
        }
        __syncthreads();
    }
#pragma unroll
    for (int r = 0; r < 4; r++)
#pragma unroll
        for (int c = 0; c < 4; c++)
            C[(4 * tr + r) * N + n0 + 4 * tc + c] = acc[r][c];
}

// Sum 8 Wt partials -> fp16 hi/lo packed pairs.
__global__ void k_cvt() {
    int i = blockIdx.x * blockDim.x + threadIdx.x;
    float w0 = 0.f, w1 = 0.f;
#pragma unroll
    for (int p = 0; p < 8; p++) {
        w0 += g_P3[p][2 * i];
        w1 += g_P3[p][2 * i + 1];
    }
    uint32_t hi, lo;
    hsplit2(w0, w1, hi, lo);
    g_WHi[i] = hi;
    g_WLo[i] = lo;
}

// Projection + fused cov partials. grid(NTB,64), 256 thr, dyn smem 71680.
__global__ __launch_bounds__(256, 2) void k_proj_cov(const float* __restrict__ x) {
    extern __shared__ __align__(16) unsigned char sm[];
    const int OW0 = 0, OW1 = 18432, OX0 = 36864, OX1 = 54272;
    __shared__ float rs[2][64];
    int tid = threadIdx.x, w = tid >> 5, lane = tid & 31;
    int b = blockIdx.y, t0 = blockIdx.x * 128;
    uint32_t sb = smem_u32(sm);
    const float* xb = x + (size_t)b * 1024 * 1200;
    int wr = (w >> 1) * 16, wc = (w & 1) * 64;
    int g = lane >> 2, tq = lane & 3;
    int arow = wr + (lane & 15), asel = 8 * (lane >> 4);
    int wm = tid >> 2, wq = 8 * (tid & 3);
    float acc[8][4] = {};

    for (int pc = 0; pc <= 16; pc++) {
        uint4 wh0, wh1, wl0, wl1;
        float4 xv[8];
        if (pc < 16) {
            const uint4* pH = (const uint4*)&g_WHi[wm * 512 + pc * 32 + wq];
            const uint4* pL = (const uint4*)&g_WLo[wm * 512 + pc * 32 + wq];
            wh0 = pH[0]; wh1 = pH[1]; wl0 = pL[0]; wl1 = pL[1];
#pragma unroll
            for (int i = 0; i < 8; i++) {
                int lin = tid + 256 * i, k = lin >> 5, tt = t0 + 4 * (lin & 31);
                xv[i] = (tt < 1200) ? *(const float4*)(xb + (size_t)(pc * 64 + k) * 1200 + tt)
                                    : make_float4(0.f, 0.f, 0.f, 0.f);
            }
        }
        if (pc > 0) {
            uint32_t wb = sb + (((pc - 1) & 1) ? OW1 : OW0);
            uint32_t xba = sb + (((pc - 1) & 1) ? OX1 : OX0);
#pragma unroll
            for (int ks = 0; ks < 4; ks++) {
                int kk = 16 * ks;
                uint32_t ah[4], al[4];
                uint32_t aa = wb + arow * 144 + (kk + asel) * 2;
                ldmA(ah, aa);
                ldmA(al, aa + 9216);
#pragma unroll
                for (int nb = 0; nb < 4; nb++) {
                    uint32_t r[4];
                    ldmBT(r, xba + (kk + (lane & 15)) * 272 + (wc + 16 * nb + asel) * 2);
                    mma(acc[2 * nb],     ah, r[0], r[1]);
                    mma(acc[2 * nb],     al, r[0], r[1]);
                    mma(acc[2 * nb + 1], ah, r[2], r[3]);
                    mma(acc[2 * nb + 1], al, r[2], r[3]);
                }
            }
        }
        if (pc < 16) {
            unsigned char* dW = sm + ((pc & 1) ? OW1 : OW0) + wm * 144 + wq * 4;
            *(uint4*)dW = wh0; *(uint4*)(dW + 16) = wh1;
            *(uint4*)(dW + 9216) = wl0; *(uint4*)(dW + 9216 + 16) = wl1;
            unsigned char* dX = sm + ((pc & 1) ? OX1 : OX0);
#pragma unroll
            for (int i = 0; i < 8; i++) {
                int lin = tid + 256 * i, k = lin >> 5, t4 = lin & 31;
                uint2 p;
                p.x = cvt2h(xv[i].x, xv[i].y);
                p.y = cvt2h(xv[i].z, xv[i].w);
                *(uint2*)(dX + k * 272 + 8 * t4) = p;
            }
        }
        __syncthreads();
    }

    {
        float s0 = 0.f, s1 = 0.f;
#pragma unroll
        for (int nf = 0; nf < 8; nf++) {
            s0 += acc[nf][0] + acc[nf][1];
            s1 += acc[nf][2] + acc[nf][3];
        }
        s0 += __shfl_xor_sync(0xffffffffu, s0, 1);
        s0 += __shfl_xor_sync(0xffffffffu, s0, 2);
        s1 += __shfl_xor_sync(0xffffffffu, s1, 1);
        s1 += __shfl_xor_sync(0xffffffffu, s1, 2);
        if (tq == 0) { rs[w & 1][wr + g] = s0; rs[w & 1][wr + g + 8] = s1; }
    }
    // stage Y as single fp16, layout [m][t], stride 272B
    unsigned char* Yh = sm + OX0;
#pragma unroll
    for (int nf = 0; nf < 8; nf++) {
        int c0 = wc + 8 * nf + 2 * tq;
        *(uint32_t*)(Yh + (wr + g) * 272 + c0 * 2)     = cvt2h(acc[nf][0], acc[nf][1]);
        *(uint32_t*)(Yh + (wr + g + 8) * 272 + c0 * 2) = cvt2h(acc[nf][2], acc[nf][3]);
    }
    __syncthreads();
    if (tid < 64) g_rsumP[blockIdx.x][b * 64 + tid] = rs[0][tid] + rs[1][tid];

    // cov = Y Y^T via tensor cores (single fp16 Y)
    {
        int cr = (w & 3) * 16, cn = (w >> 2) * 32;
        float cc[4][4] = {};
        uint32_t yh = sb + OX0;
#pragma unroll
        for (int kk = 0; kk < 128; kk += 16) {
            uint32_t ah[4], bh[8];
            ldmA(ah, yh + (cr + (lane & 15)) * 272 + (kk + asel) * 2);
            uint32_t ba = (cn + (lane & 15)) * 272 + (kk + asel) * 2;
            ldmA(bh, yh + ba); ldmA(bh + 4, yh + ba + 16 * 272);
#pragma unroll
            for (int jb = 0; jb < 4; jb++) {
                int base = (jb >> 1) * 4 + (jb & 1);
                mma(cc[jb], ah, bh[base], bh[base + 2]);
            }
        }
        float* Cp = g_Cpart[blockIdx.x][b];
#pragma unroll
        for (int jb = 0; jb < 4; jb++) {
            int col = cn + 8 * jb + 2 * tq;
            *(float2*)&Cp[(cr + g) * 64 + col]     = make_float2(cc[jb][0], cc[jb][1]);
            *(float2*)&Cp[(cr + g + 8) * 64 + col] = make_float2(cc[jb][2], cc[jb][3]);
        }
    }
}

// tensor 64x64 step on fp16 hi/lo pairs: D = s*(A@B) + dg*I. out32: fp32 D.
__device__ __noinline__ void mm64t(unsigned char* sm, uint32_t sb, int oA, int oB, int oD,
                                   float s, float dg, int tid, int out32) {
    int w = tid >> 5, lane = tid & 31, g = lane >> 2, tq = lane & 3;
    int cr = (w & 3) * 16, cn = (w >> 2) * 32;
    int lr = lane & 15, ls = 8 * (lane >> 4);
    float acc[4][4] = {};
#pragma unroll
    for (int kk = 0; kk < 64; kk += 16) {
        uint32_t ah[4], al[4], bh[8], bl[8];
        uint32_t aa = sb + oA + (cr + lr) * 144 + (kk + ls) * 2;
        ldmA(ah, aa); ldmA(al, aa + 9216);
        uint32_t ba = sb + oB + (kk + lr) * 144 + (cn + ls) * 2;
        ldmBT(bh, ba); ldmBT(bh + 4, ba + 32);
        ldmBT(bl, ba + 9216); ldmBT(bl + 4, ba + 9216 + 32);
#pragma unroll
        for (int jb = 0; jb < 4; jb++) {
            int base = (jb >> 1) * 4 + (jb & 1) * 2;
            mma(acc[jb], ah, bh[base], bh[base + 1]);
            mma(acc[jb], ah, bl[base], bl[base + 1]);
            mma(acc[jb], al, bh[base], bh[base + 1]);
        }
    }
    if (out32) {
        float* Df = (float*)(sm + oD);
#pragma unroll
        for (int jb = 0; jb < 4; jb++) {
            int col = cn + 8 * jb + 2 * tq;
#pragma unroll
            for (int h2 = 0; h2 < 2; h2++) {
                int row = cr + g + 8 * h2;
                float v0 = s * acc[jb][2 * h2]     + ((row == col) ? dg : 0.f);
                float v1 = s * acc[jb][2 * h2 + 1] + ((row == col + 1) ? dg : 0.f);
                *(float2*)&Df[row * 64 + col] = make_float2(v0, v1);
            }
        }
    } else {
        __half* Dh = (__half*)(sm + oD);
        __half* Dl = (__half*)(sm + oD + 9216);
#pragma unroll
        for (int jb = 0; jb < 4; jb++) {
            int col = cn + 8 * jb + 2 * tq;
#pragma unroll
            for (int h2 = 0; h2 < 2; h2++) {
                int row = cr + g + 8 * h2;
                float v0 = s * acc[jb][2 * h2]     + ((row == col) ? dg : 0.f);
                float v1 = s * acc[jb][2 * h2 + 1] + ((row == col + 1) ? dg : 0.f);
                uint32_t hi, lo;
                hsplit2(v0, v1, hi, lo);
                *(uint32_t*)(Dh + row * 72 + col) = hi;
                *(uint32_t*)(Dl + row * 72 + col) = lo;
            }
        }
    }
    __syncthreads();
}

// Fused reduce + center + logm + linear head. One block per batch matrix.
__global__ __launch_bounds__(256) void k_logm(const float* __restrict__ lw,
                                              const float* __restrict__ lb,
                                              float* __restrict__ out) {
    extern __shared__ __align__(16) unsigned char sm[];
    __shared__ float s_r[64], red[64];
    __shared__ float s_inva, s_lna;
    int b = blockIdx.x, tid = threadIdx.x, w = tid >> 5, lane = tid & 31;
    uint32_t sb = smem_u32(sm);
    const float iT = 1.f / 1200.f, iT1 = 1.f / 1199.f;

    if (tid < 64) {
        float v = 0.f;
#pragma unroll
        for (int p = 0; p < NTB; p++) v += g_rsumP[p][b * 64 + tid];
        s_r[tid] = v;
    }
    __syncthreads();
    if (tid < 64) {
        float d = 0.f;
#pragma unroll
        for (int p = 0; p < NTB; p++) d += g_Cpart[p][b][tid * 65];
        red[tid] = (d - s_r[tid] * s_r[tid] * iT) * iT1;
    }
    __syncthreads();
    if (tid == 0) {
        float tr = 0.f;
        for (int i = 0; i < 64; i++) tr += red[i];
        float al = tr * (1.f / 64.f);
        s_inva = 1.f / al; s_lna = logf(al);
    }
    __syncthreads();
    float inva = s_inva;

    int oY = 0, oZ = 18432, oT = 36864, oU = 55296;
#pragma unroll
    for (int i = 0; i < 16; i++) {
        int lin = tid + 256 * i, r = lin >> 6, c = lin & 63;
        float v = 0.f;
#pragma unroll
        for (int p = 0; p < NTB; p++) v += g_Cpart[p][b][lin];
        float a = (v - s_r[r] * s_r[c] * iT) * iT1 * inva;
        __half h = __float2half(a);
        ((__half*)(sm + oY))[r * 72 + c] = h;
        ((__half*)(sm + oY + 9216))[r * 72 + c] = __float2half(a - __half2float(h));
        ((__half*)(sm + oZ))[r * 72 + c] = __float2half((r == c) ? 1.f : 0.f);
        ((__half*)(sm + oZ + 9216))[r * 72 + c] = __float2half(0.f);
    }
    __syncthreads();

    for (int it = 0; it < 5; it++) {
        mm64t(sm, sb, oZ, oY, oT, -1.f, 3.f, tid, 0);
        mm64t(sm, sb, oY, oT, oU, 0.5f, 0.f, tid, 0);
        mm64t(sm, sb, oT, oZ, oY, 0.5f, 0.f, tid, 0);
        int t = oY; oY = oU; oU = oT; oT = oZ; oZ = t;
    }
    __half *SH = (__half*)(sm + oY), *SL = (__half*)(sm + oY + 9216);
    __half *MH = (__half*)(sm + oZ), *ML = (__half*)(sm + oZ + 9216);
    __half *PH = (__half*)(sm + oT), *PL = (__half*)(sm + oT + 9216);
#pragma unroll
    for (int i = 0; i < 16; i++) {
        int lin = tid + 256 * i, r = lin >> 6, c = lin & 63;
        int idx = r * 72 + c;
        float m = __half2float(SH[idx]) + __half2float(SL[idx]) - ((r == c) ? 1.f : 0.f);
        __half mh = __float2half(m);
        MH[idx] = mh; ML[idx] = __float2half(m - __half2float(mh));
        float pv = (-1.f / 10.f) * m + ((r == c) ? (1.f / 9.f) : 0.f);
        __half ph = __float2half(pv);
        PH[idx] = ph; PL[idx] = __float2half(pv - __half2float(ph));
    }
    __syncthreads();
    int oP = oT, oQ = oU;
    for (int k = 8; k >= 1; k--) {
        float ck = ((k & 1) ? 1.f : -1.f) / (float)k;
        mm64t(sm, sb, oZ, oP, oQ, 1.f, ck, tid, 0);
        int t = oP; oP = oQ; oQ = t;
    }
    mm64t(sm, sb, oZ, oP, oQ, 2.f, s_lna, tid, 1);   // fp32 logC into oQ

    float* Qf = (float*)(sm + oQ);
    for (int j = w; j < 11; j += 8) {
        const float* wj = lw + (size_t)j * 4096;
        float s = 0.f;
        for (int i = lane * 4; i < 4096; i += 128) {
            float4 qv = *(float4*)&Qf[i];
            float4 wv = *(const float4*)&wj[i];
            s += qv.x * wv.x + qv.y * wv.y + qv.z * wv.z + qv.w * wv.w;
        }
#pragma unroll
        for (int o = 16; o > 0; o >>= 1) s += __shfl_xor_sync(0xffffffffu, s, o);
        if (lane == 0) out[b * 11 + j] = s + lb[j];
    }
}

extern "C" void kernel_launch(void* const* d_in, const int* in_sizes, int n_in,
                              void* d_out, int out_size) {
    const float* x  = (const float*)d_in[0];
    const float* W1 = (const float*)d_in[1];
    const float* W2 = (const float*)d_in[2];
    const float* W3 = (const float*)d_in[3];
    const float* W4 = (const float*)d_in[4];
    const float* lw = (const float*)d_in[5];
    const float* lb = (const float*)d_in[6];
    float* out = (float*)d_out;

    float *pP1, *pP2, *pP3;
    cudaGetSymbolAddress((void**)&pP1, g_P1);
    cudaGetSymbolAddress((void**)&pP2, g_P2);
    cudaGetSymbolAddress((void**)&pP3, g_P3);

    static bool done = false;
    if (!done) {
        cudaFuncSetAttribute(k_proj_cov, cudaFuncAttributeMaxDynamicSharedMemorySize, 71680);
        cudaFuncSetAttribute(k_logm, cudaFuncAttributeMaxDynamicSharedMemorySize, 73728);
        done = true;
    }
    k_fold1<<<dim3(4, 4), 256>>>(W4, W3);                             // P1[4] partials
    k_ntk<4><<<dim3(8, 8),  256>>>(pP1, W2, pP2, 256, 32, 512);       // P2[8] partials
    k_ntk<8><<<dim3(16, 8), 256>>>(pP2, W1, pP3, 512, 64, 1024);      // P3[8] partials
    k_cvt<<<128, 256>>>();                                            // -> fp16 hi/lo
    k_proj_cov<<<dim3(NTB, 64), 256, 71680>>>(x);
    k_logm<<<64, 256, 73728>>>(lw, lb, out);
}

// round 15
// speedup vs baseline: 1.7107x; 1.0297x over previous
#include <cuda_runtime.h>
#include <cuda_fp16.h>
#include <cstdint>

#define NTB 10
__device__ float g_P1[4][64 * 256];
__device__ float g_P2[8][64 * 512];
__device__ float g_P3[8][64 * 1024];
__device__ uint32_t g_WHi[64 * 512];
__device__ uint32_t g_WLo[64 * 512];
__device__ float g_Cpart[NTB][64][4096];
__device__ float g_rsumP[NTB][4096];
__device__ int g_doneB[64];
__device__ int g_cntW[16];

__device__ __forceinline__ uint32_t smem_u32(const void* p) {
    uint32_t a;
    asm("{ .reg .u64 t; cvta.to.shared.u64 t, %1; cvt.u32.u64 %0, t; }" : "=r"(a) : "l"(p));
    return a;
}
__device__ __forceinline__ uint32_t cvt2h(float lo, float hi) {
    uint32_t r;
    asm("cvt.rn.f16x2.f32 %0, %1, %2;" : "=r"(r) : "f"(hi), "f"(lo));
    return r;
}
__device__ __forceinline__ uint32_t hpack(__half a, __half b) {
    return (uint32_t)__half_as_ushort(a) | ((uint32_t)__half_as_ushort(b) << 16);
}
__device__ __forceinline__ void hsplit2(float v0, float v1, uint32_t& hi, uint32_t& lo) {
    __half h0 = __float2half(v0), h1 = __float2half(v1);
    hi = hpack(h0, h1);
    lo = hpack(__float2half(v0 - __half2float(h0)), __float2half(v1 - __half2float(h1)));
}
__device__ __forceinline__ void ldmA(uint32_t* r, uint32_t a) {
    asm volatile("ldmatrix.sync.aligned.m8n8.x4.shared.b16 {%0,%1,%2,%3}, [%4];"
                 : "=r"(r[0]), "=r"(r[1]), "=r"(r[2]), "=r"(r[3]) : "r"(a));
}
__device__ __forceinline__ void ldmBT(uint32_t* r, uint32_t a) {
    asm volatile("ldmatrix.sync.aligned.m8n8.x4.trans.shared.b16 {%0,%1,%2,%3}, [%4];"
                 : "=r"(r[0]), "=r"(r[1]), "=r"(r[2]), "=r"(r[3]) : "r"(a));
}
__device__ __forceinline__ void mma(float* c, const uint32_t a[4], uint32_t b0, uint32_t b1) {
    asm volatile("mma.sync.aligned.m16n8k16.row.col.f32.f16.f16.f32 "
                 "{%0,%1,%2,%3},{%4,%5,%6,%7},{%8,%9},{%0,%1,%2,%3};"
                 : "+f"(c[0]), "+f"(c[1]), "+f"(c[2]), "+f"(c[3])
                 : "r"(a[0]), "r"(a[1]), "r"(a[2]), "r"(a[3]), "r"(b0), "r"(b1));
}

// P1[ks][i,j] = sum_{k in slice} W4[k,i]*W3[j,k].  grid(4 n, 4 ksplit). Also zeroes counters.
__global__ __launch_bounds__(256) void k_fold1(const float* __restrict__ W4,
                                               const float* __restrict__ W3) {
    __shared__ float As[64][33], Bs[64][33];
    int n0 = blockIdx.x * 64, k0 = blockIdx.y * 32;
    int tid = threadIdx.x, tr = tid >> 4, tc = tid & 15;
    if (blockIdx.x == 0 && blockIdx.y == 0) {
        if (tid < 64) g_doneB[tid] = 0;
        else if (tid < 80) g_cntW[tid - 64] = 0;
    }
    float acc[4][4] = {};
#pragma unroll
    for (int i = 0; i < 8; i++) {
        int lin = tid + 256 * i, m = lin >> 5, k = lin & 31;
        As[m][k] = W4[(k0 + k) * 64 + m];
        Bs[m][k] = W3[(n0 + m) * 128 + k0 + k];
    }
    __syncthreads();
#pragma unroll 4
    for (int kk = 0; kk < 32; kk++) {
        float a[4], b[4];
#pragma unroll
        for (int r = 0; r < 4; r++) a[r] = As[4 * tr + r][kk];
#pragma unroll
        for (int c = 0; c < 4; c++) b[c] = Bs[4 * tc + c][kk];
#pragma unroll
        for (int r = 0; r < 4; r++)
#pragma unroll
            for (int c = 0; c < 4; c++) acc[r][c] += a[r] * b[c];
    }
#pragma unroll
    for (int r = 0; r < 4; r++)
#pragma unroll
        for (int c = 0; c < 4; c++)
            g_P1[blockIdx.y][(4 * tr + r) * 256 + n0 + 4 * tc + c] = acc[r][c];
}

// NT GEMM, K-split; A = sum of NP partials (compile-time unrolled, full MLP).
template <int NP>
__global__ __launch_bounds__(256) void k_ntk(const float* __restrict__ A,
                                             const float* __restrict__ Bm,
                                             float* __restrict__ Cout,
                                             int Ktot, int Kslice, int N) {
    __shared__ float As[64][33], Bs[64][33];
    int n0 = blockIdx.x * 64, koff = blockIdx.y * Kslice;
    float* C = Cout + (size_t)blockIdx.y * 64 * N;
    int tid = threadIdx.x, tr = tid >> 4, tc = tid & 15;
    float acc[4][4] = {};
    for (int k0 = koff; k0 < koff + Kslice; k0 += 32) {
#pragma unroll
        for (int i = 0; i < 8; i++) {
            int lin = tid + 256 * i, m = lin >> 5, k = lin & 31;
            float a = 0.f;
#pragma unroll
            for (int p = 0; p < NP; p++) a += A[(size_t)p * 64 * Ktot + m * Ktot + k0 + k];
            As[m][k] = a;
            Bs[m][k] = Bm[(n0 + m) * Ktot + k0 + k];
        }
        __syncthreads();
#pragma unroll 4
        for (int kk = 0; kk < 32; kk++) {
            float a[4], b[4];
#pragma unroll
            for (int r = 0; r < 4; r++) a[r] = As[4 * tr + r][kk];
#pragma unroll
            for (int c = 0; c < 4; c++) b[c] = Bs[4 * tc + c][kk];
#pragma unroll
            for (int r = 0; r < 4; r++)
#pragma unroll
                for (int c = 0; c < 4; c++) acc[r][c] += a[r] * b[c];
        }
        __syncthreads();
    }
#pragma unroll
    for (int r = 0; r < 4; r++)
#pragma unroll
        for (int c = 0; c < 4; c++)
            C[(4 * tr + r) * N + n0 + 4 * tc + c] = acc[r][c];
}

// GEMM3 (Ktot=512, N=1024, 8 partials in, 8-way ksplit out) + fused cvt:
// last finishing block per n-column sums the 8 partials -> fp16 hi/lo.
__global__ __launch_bounds__(256) void k_ntk8(const float* __restrict__ A,
                                              const float* __restrict__ Bm) {
    __shared__ float As[64][33], Bs[64][33];
    __shared__ int s_last;
    const int Ktot = 512, Kslice = 64, N = 1024;
    int n0 = blockIdx.x * 64, koff = blockIdx.y * Kslice;
    float* C = &g_P3[blockIdx.y][0];
    int tid = threadIdx.x, tr = tid >> 4, tc = tid & 15;
    float acc[4][4] = {};
    for (int k0 = koff; k0 < koff + Kslice; k0 += 32) {
#pragma unroll
        for (int i = 0; i < 8; i++) {
            int lin = tid + 256 * i, m = lin >> 5, k = lin & 31;
            float a = 0.f;
#pragma unroll
            for (int p = 0; p < 8; p++) a += A[(size_t)p * 64 * Ktot + m * Ktot + k0 + k];
            As[m][k] = a;
            Bs[m][k] = Bm[(n0 + m) * Ktot + k0 + k];
        }
        __syncthreads();
#pragma unroll 4
        for (int kk = 0; kk < 32; kk++) {
            float a[4], b[4];
#pragma unroll
            for (int r = 0; r < 4; r++) a[r] = As[4 * tr + r][kk];
#pragma unroll
            for (int c = 0; c < 4; c++) b[c] = Bs[4 * tc + c][kk];
#pragma unroll
            for (int r = 0; r < 4; r++)
#pragma unroll
                for (int c = 0; c < 4; c++) acc[r][c] += a[r] * b[c];
        }
        __syncthreads();
    }
#pragma unroll
    for (int r = 0; r < 4; r++)
#pragma unroll
        for (int c = 0; c < 4; c++)
            C[(4 * tr + r) * N + n0 + 4 * tc + c] = acc[r][c];
    // last-block reduction + convert for this n-column
    __syncthreads();
    if (tid == 0) {
        __threadfence();
        s_last = (atomicAdd(&g_cntW[blockIdx.x], 1) == 7);
    }
    __syncthreads();
    if (s_last) {
        __threadfence();
        for (int i = tid; i < 2048; i += 256) {          // 64 rows x 32 pair-cols
            int m = i >> 5, n = n0 + 2 * (i & 31);
            float w0 = 0.f, w1 = 0.f;
#pragma unroll
            for (int p = 0; p < 8; p++) {
                w0 += g_P3[p][m * 1024 + n];
                w1 += g_P3[p][m * 1024 + n + 1];
            }
            uint32_t hi, lo;
            hsplit2(w0, w1, hi, lo);
            g_WHi[m * 512 + (n >> 1)] = hi;
            g_WLo[m * 512 + (n >> 1)] = lo;
        }
    }
}

// tensor 64x64 step on fp16 hi/lo pairs: D = s*(A@B) + dg*I. out32: fp32 D.
__device__ __noinline__ void mm64t(unsigned char* sm, uint32_t sb, int oA, int oB, int oD,
                                   float s, float dg, int tid, int out32) {
    int w = tid >> 5, lane = tid & 31, g = lane >> 2, tq = lane & 3;
    int cr = (w & 3) * 16, cn = (w >> 2) * 32;
    int lr = lane & 15, ls = 8 * (lane >> 4);
    float acc[4][4] = {};
#pragma unroll
    for (int kk = 0; kk < 64; kk += 16) {
        uint32_t ah[4], al[4], bh[8], bl[8];
        uint32_t aa = sb + oA + (cr + lr) * 144 + (kk + ls) * 2;
        ldmA(ah, aa); ldmA(al, aa + 9216);
        uint32_t ba = sb + oB + (kk + lr) * 144 + (cn + ls) * 2;
        ldmBT(bh, ba); ldmBT(bh + 4, ba + 32);
        ldmBT(bl, ba + 9216); ldmBT(bl + 4, ba + 9216 + 32);
#pragma unroll
        for (int jb = 0; jb < 4; jb++) {
            int base = (jb >> 1) * 4 + (jb & 1) * 2;
            mma(acc[jb], ah, bh[base], bh[base + 1]);
            mma(acc[jb], ah, bl[base], bl[base + 1]);
            mma(acc[jb], al, bh[base], bh[base + 1]);
        }
    }
    if (out32) {
        float* Df = (float*)(sm + oD);
#pragma unroll
        for (int jb = 0; jb < 4; jb++) {
            int col = cn + 8 * jb + 2 * tq;
#pragma unroll
            for (int h2 = 0; h2 < 2; h2++) {
                int row = cr + g + 8 * h2;
                float v0 = s * acc[jb][2 * h2]     + ((row == col) ? dg : 0.f);
                float v1 = s * acc[jb][2 * h2 + 1] + ((row == col + 1) ? dg : 0.f);
                *(float2*)&Df[row * 64 + col] = make_float2(v0, v1);
            }
        }
    } else {
        __half* Dh = (__half*)(sm + oD);
        __half* Dl = (__half*)(sm + oD + 9216);
#pragma unroll
        for (int jb = 0; jb < 4; jb++) {
            int col = cn + 8 * jb + 2 * tq;
#pragma unroll
            for (int h2 = 0; h2 < 2; h2++) {
                int row = cr + g + 8 * h2;
                float v0 = s * acc[jb][2 * h2]     + ((row == col) ? dg : 0.f);
                float v1 = s * acc[jb][2 * h2 + 1] + ((row == col + 1) ? dg : 0.f);
                uint32_t hi, lo;
                hsplit2(v0, v1, hi, lo);
                *(uint32_t*)(Dh + row * 72 + col) = hi;
                *(uint32_t*)(Dl + row * 72 + col) = lo;
            }
        }
    }
    __syncthreads();
}

// Fused proj+cov (blocks 0..639, batch-major) and logm+linear (blocks 640..703,
// spinning on per-batch done counters). One launch; logm overlaps proj's tail.
__global__ __launch_bounds__(256, 2) void k_projlogm(const float* __restrict__ x,
                                                     const float* __restrict__ lw,
                                                     const float* __restrict__ lb,
                                                     float* __restrict__ out) {
    extern __shared__ __align__(16) unsigned char sm[];
    int tid = threadIdx.x, w = tid >> 5, lane = tid & 31;
    uint32_t sb = smem_u32(sm);

    if (blockIdx.x < 640) {
        // ---------------- projection + cov partials ----------------
        const int OW0 = 0, OW1 = 18432, OX0 = 36864, OX1 = 54272;
        __shared__ float rs[2][64];
        int b = blockIdx.x / 10, tblk = blockIdx.x % 10, t0 = tblk * 128;
        const float* xb = x + (size_t)b * 1024 * 1200;
        int wr = (w >> 1) * 16, wc = (w & 1) * 64;
        int g = lane >> 2, tq = lane & 3;
        int arow = wr + (lane & 15), asel = 8 * (lane >> 4);
        int wm = tid >> 2, wq = 8 * (tid & 3);
        float acc[8][4] = {};

        for (int pc = 0; pc <= 16; pc++) {
            uint4 wh0, wh1, wl0, wl1;
            float4 xv[8];
            if (pc < 16) {
                const uint4* pH = (const uint4*)&g_WHi[wm * 512 + pc * 32 + wq];
                const uint4* pL = (const uint4*)&g_WLo[wm * 512 + pc * 32 + wq];
                wh0 = pH[0]; wh1 = pH[1]; wl0 = pL[0]; wl1 = pL[1];
#pragma unroll
                for (int i = 0; i < 8; i++) {
                    int lin = tid + 256 * i, k = lin >> 5, tt = t0 + 4 * (lin & 31);
                    xv[i] = (tt < 1200) ? *(const float4*)(xb + (size_t)(pc * 64 + k) * 1200 + tt)
                                        : make_float4(0.f, 0.f, 0.f, 0.f);
                }
            }
            if (pc > 0) {
                uint32_t wb = sb + (((pc - 1) & 1) ? OW1 : OW0);
                uint32_t xba = sb + (((pc - 1) & 1) ? OX1 : OX0);
#pragma unroll
                for (int ks = 0; ks < 4; ks++) {
                    int kk = 16 * ks;
                    uint32_t ah[4], al[4];
                    uint32_t aa = wb + arow * 144 + (kk + asel) * 2;
                    ldmA(ah, aa);
                    ldmA(al, aa + 9216);
#pragma unroll
                    for (int nb = 0; nb < 4; nb++) {
                        uint32_t r[4];
                        ldmBT(r, xba + (kk + (lane & 15)) * 272 + (wc + 16 * nb + asel) * 2);
                        mma(acc[2 * nb],     ah, r[0], r[1]);
                        mma(acc[2 * nb],     al, r[0], r[1]);
                        mma(acc[2 * nb + 1], ah, r[2], r[3]);
                        mma(acc[2 * nb + 1], al, r[2], r[3]);
                    }
                }
            }
            if (pc < 16) {
                unsigned char* dW = sm + ((pc & 1) ? OW1 : OW0) + wm * 144 + wq * 4;
                *(uint4*)dW = wh0; *(uint4*)(dW + 16) = wh1;
                *(uint4*)(dW + 9216) = wl0; *(uint4*)(dW + 9216 + 16) = wl1;
                unsigned char* dX = sm + ((pc & 1) ? OX1 : OX0);
#pragma unroll
                for (int i = 0; i < 8; i++) {
                    int lin = tid + 256 * i, k = lin >> 5, t4 = lin & 31;
                    uint2 p;
                    p.x = cvt2h(xv[i].x, xv[i].y);
                    p.y = cvt2h(xv[i].z, xv[i].w);
                    *(uint2*)(dX + k * 272 + 8 * t4) = p;
                }
            }
            __syncthreads();
        }
        {
            float s0 = 0.f, s1 = 0.f;
#pragma unroll
            for (int nf = 0; nf < 8; nf++) {
                s0 += acc[nf][0] + acc[nf][1];
                s1 += acc[nf][2] + acc[nf][3];
            }
            s0 += __shfl_xor_sync(0xffffffffu, s0, 1);
            s0 += __shfl_xor_sync(0xffffffffu, s0, 2);
            s1 += __shfl_xor_sync(0xffffffffu, s1, 1);
            s1 += __shfl_xor_sync(0xffffffffu, s1, 2);
            if (tq == 0) { rs[w & 1][wr + g] = s0; rs[w & 1][wr + g + 8] = s1; }
        }
        unsigned char* Yh = sm + OX0;
#pragma unroll
        for (int nf = 0; nf < 8; nf++) {
            int c0 = wc + 8 * nf + 2 * tq;
            *(uint32_t*)(Yh + (wr + g) * 272 + c0 * 2)     = cvt2h(acc[nf][0], acc[nf][1]);
            *(uint32_t*)(Yh + (wr + g + 8) * 272 + c0 * 2) = cvt2h(acc[nf][2], acc[nf][3]);
        }
        __syncthreads();
        if (tid < 64) g_rsumP[tblk][b * 64 + tid] = rs[0][tid] + rs[1][tid];
        {
            int cr = (w & 3) * 16, cn = (w >> 2) * 32;
            float cc[4][4] = {};
            uint32_t yh = sb + OX0;
#pragma unroll
            for (int kk = 0; kk < 128; kk += 16) {
                uint32_t ah[4], bh[8];
                ldmA(ah, yh + (cr + (lane & 15)) * 272 + (kk + asel) * 2);
                uint32_t ba = (cn + (lane & 15)) * 272 + (kk + asel) * 2;
                ldmA(bh, yh + ba); ldmA(bh + 4, yh + ba + 16 * 272);
#pragma unroll
                for (int jb = 0; jb < 4; jb++) {
                    int base = (jb >> 1) * 4 + (jb & 1);
                    mma(cc[jb], ah, bh[base], bh[base + 2]);
                }
            }
            float* Cp = g_Cpart[tblk][b];
#pragma unroll
            for (int jb = 0; jb < 4; jb++) {
                int col = cn + 8 * jb + 2 * tq;
                *(float2*)&Cp[(cr + g) * 64 + col]     = make_float2(cc[jb][0], cc[jb][1]);
                *(float2*)&Cp[(cr + g + 8) * 64 + col] = make_float2(cc[jb][2], cc[jb][3]);
            }
        }
        __syncthreads();
        if (tid == 0) {
            __threadfence();
            atomicAdd(&g_doneB[b], 1);
        }
        return;
    }

    // ---------------- logm + linear head ----------------
    int b = blockIdx.x - 640;
    __shared__ float s_r[64], red[64];
    __shared__ float s_inva, s_lna;
    const float iT = 1.f / 1200.f, iT1 = 1.f / 1199.f;

    if (tid == 0) {
        while (atomicAdd(&g_doneB[b], 0) < NTB) {}
        __threadfence();
    }
    __syncthreads();

    if (tid < 64) {
        float v = 0.f;
#pragma unroll
        for (int p = 0; p < NTB; p++) v += g_rsumP[p][b * 64 + tid];
        s_r[tid] = v;
    }
    __syncthreads();
    if (tid < 64) {
        float d = 0.f;
#pragma unroll
        for (int p = 0; p < NTB; p++) d += g_Cpart[p][b][tid * 65];
        red[tid] = (d - s_r[tid] * s_r[tid] * iT) * iT1;
    }
    __syncthreads();
    if (tid == 0) {
        float tr = 0.f;
        for (int i = 0; i < 64; i++) tr += red[i];
        float al = tr * (1.f / 64.f);
        s_inva = 1.f / al; s_lna = logf(al);
    }
    __syncthreads();
    float inva = s_inva;

    int oY = 0, oZ = 18432, oT = 36864, oU = 55296;
#pragma unroll
    for (int i = 0; i < 16; i++) {
        int lin = tid + 256 * i, r = lin >> 6, c = lin & 63;
        float v = 0.f;
#pragma unroll
        for (int p = 0; p < NTB; p++) v += g_Cpart[p][b][lin];
        float a = (v - s_r[r] * s_r[c] * iT) * iT1 * inva;
        __half h = __float2half(a);
        ((__half*)(sm + oY))[r * 72 + c] = h;
        ((__half*)(sm + oY + 9216))[r * 72 + c] = __float2half(a - __half2float(h));
        ((__half*)(sm + oZ))[r * 72 + c] = __float2half((r == c) ? 1.f : 0.f);
        ((__half*)(sm + oZ + 9216))[r * 72 + c] = __float2half(0.f);
    }
    __syncthreads();

    for (int it = 0; it < 5; it++) {
        mm64t(sm, sb, oZ, oY, oT, -1.f, 3.f, tid, 0);
        mm64t(sm, sb, oY, oT, oU, 0.5f, 0.f, tid, 0);
        mm64t(sm, sb, oT, oZ, oY, 0.5f, 0.f, tid, 0);
        int t = oY; oY = oU; oU = oT; oT = oZ; oZ = t;
    }
    __half *SH = (__half*)(sm + oY), *SL = (__half*)(sm + oY + 9216);
    __half *MH = (__half*)(sm + oZ), *ML = (__half*)(sm + oZ + 9216);
    __half *PH = (__half*)(sm + oT), *PL = (__half*)(sm + oT + 9216);
#pragma unroll
    for (int i = 0; i < 16; i++) {
        int lin = tid + 256 * i, r = lin >> 6, c = lin & 63;
        int idx = r * 72 + c;
        float m = __half2float(SH[idx]) + __half2float(SL[idx]) - ((r == c) ? 1.f : 0.f);
        __half mh = __float2half(m);
        MH[idx] = mh; ML[idx] = __float2half(m - __half2float(mh));
        float pv = (-1.f / 10.f) * m + ((r == c) ? (1.f / 9.f) : 0.f);
        __half ph = __float2half(pv);
        PH[idx] = ph; PL[idx] = __float2half(pv - __half2float(ph));
    }
    __syncthreads();
    int oP = oT, oQ = oU;
    for (int k = 8; k >= 1; k--) {
        float ck = ((k & 1) ? 1.f : -1.f) / (float)k;
        mm64t(sm, sb, oZ, oP, oQ, 1.f, ck, tid, 0);
        int t = oP; oP = oQ; oQ = t;
    }
    mm64t(sm, sb, oZ, oP, oQ, 2.f, s_lna, tid, 1);   // fp32 logC into oQ

    float* Qf = (float*)(sm + oQ);
    for (int j = w; j < 11; j += 8) {
        const float* wj = lw + (size_t)j * 4096;
        float s = 0.f;
        for (int i = lane * 4; i < 4096; i += 128) {
            float4 qv = *(float4*)&Qf[i];
            float4 wv = *(const float4*)&wj[i];
            s += qv.x * wv.x + qv.y * wv.y + qv.z * wv.z + qv.w * wv.w;
        }
#pragma unroll
        for (int o = 16; o > 0; o >>= 1) s += __shfl_xor_sync(0xffffffffu, s, o);
        if (lane == 0) out[b * 11 + j] = s + lb[j];
    }
}

extern "C" void kernel_launch(void* const* d_in, const int* in_sizes, int n_in,
                              void* d_out, int out_size) {
    const float* x  = (const float*)d_in[0];
    const float* W1 = (const float*)d_in[1];
    const float* W2 = (const float*)d_in[2];
    const float* W3 = (const float*)d_in[3];
    const float* W4 = (const float*)d_in[4];
    const float* lw = (const float*)d_in[5];
    const float* lb = (const float*)d_in[6];
    float* out = (float*)d_out;

    float *pP1, *pP2;
    cudaGetSymbolAddress((void**)&pP1, g_P1);
    cudaGetSymbolAddress((void**)&pP2, g_P2);

    static bool done = false;
    if (!done) {
        cudaFuncSetAttribute(k_projlogm, cudaFuncAttributeMaxDynamicSharedMemorySize, 73728);
        done = true;
    }
    k_fold1<<<dim3(4, 4), 256>>>(W4, W3);                        // P1[4] partials + zero counters
    k_ntk<4><<<dim3(8, 8), 256>>>(pP1, W2, pP2, 256, 32, 512);   // P2[8] partials
    k_ntk8<<<dim3(16, 8), 256>>>(pP2, W1);                       // P3 partials + fused cvt
    k_projlogm<<<704, 256, 73728>>>(x, lw, lb, out);             // proj+cov, overlapped logm
}

// round 16
// speedup vs baseline: 1.7550x; 1.0259x over previous
#include <cuda_runtime.h>
#include <cuda_fp16.h>
#include <cstdint>

#define NTB 10
__device__ float g_P1[4][64 * 256];
__device__ float g_P2[8][64 * 512];
__device__ float g_P3[8][64 * 1024];
__device__ uint32_t g_WHi[64 * 512];
__device__ uint32_t g_WLo[64 * 512];
__device__ float g_Cpart[NTB][64][4096];
__device__ float g_rsumP[NTB][4096];
__device__ int g_doneB[64];
__device__ int g_bar[4];

__device__ __forceinline__ uint32_t smem_u32(const void* p) {
    uint32_t a;
    asm("{ .reg .u64 t; cvta.to.shared.u64 t, %1; cvt.u32.u64 %0, t; }" : "=r"(a) : "l"(p));
    return a;
}
__device__ __forceinline__ uint32_t cvt2h(float lo, float hi) {
    uint32_t r;
    asm("cvt.rn.f16x2.f32 %0, %1, %2;" : "=r"(r) : "f"(hi), "f"(lo));
    return r;
}
__device__ __forceinline__ uint32_t hpack(__half a, __half b) {
    return (uint32_t)__half_as_ushort(a) | ((uint32_t)__half_as_ushort(b) << 16);
}
__device__ __forceinline__ void hsplit2(float v0, float v1, uint32_t& hi, uint32_t& lo) {
    __half h0 = __float2half(v0), h1 = __float2half(v1);
    hi = hpack(h0, h1);
    lo = hpack(__float2half(v0 - __half2float(h0)), __float2half(v1 - __half2float(h1)));
}
__device__ __forceinline__ void ldmA(uint32_t* r, uint32_t a) {
    asm volatile("ldmatrix.sync.aligned.m8n8.x4.shared.b16 {%0,%1,%2,%3}, [%4];"
                 : "=r"(r[0]), "=r"(r[1]), "=r"(r[2]), "=r"(r[3]) : "r"(a));
}
__device__ __forceinline__ void ldmBT(uint32_t* r, uint32_t a) {
    asm volatile("ldmatrix.sync.aligned.m8n8.x4.trans.shared.b16 {%0,%1,%2,%3}, [%4];"
                 : "=r"(r[0]), "=r"(r[1]), "=r"(r[2]), "=r"(r[3]) : "r"(a));
}
__device__ __forceinline__ void mma(float* c, const uint32_t a[4], uint32_t b0, uint32_t b1) {
    asm volatile("mma.sync.aligned.m16n8k16.row.col.f32.f16.f16.f32 "
                 "{%0,%1,%2,%3},{%4,%5,%6,%7},{%8,%9},{%0,%1,%2,%3};"
                 : "+f"(c[0]), "+f"(c[1]), "+f"(c[2]), "+f"(c[3])
                 : "r"(a[0]), "r"(a[1]), "r"(a[2]), "r"(a[3]), "r"(b0), "r"(b1));
}

// ---- fold bodies (shared mem passed in; As/Bs are [64][33] floats) ----
__device__ void fold1_body(const float* __restrict__ W4, const float* __restrict__ W3,
                           float* As, float* Bs, int n0, int k0, int tid) {
    int tr = tid >> 4, tc = tid & 15;
    float acc[4][4] = {};
#pragma unroll
    for (int i = 0; i < 8; i++) {
        int lin = tid + 256 * i, m = lin >> 5, k = lin & 31;
        As[m * 33 + k] = W4[(k0 + k) * 64 + m];
        Bs[m * 33 + k] = W3[(n0 + m) * 128 + k0 + k];
    }
    __syncthreads();
#pragma unroll 4
    for (int kk = 0; kk < 32; kk++) {
        float a[4], b[4];
#pragma unroll
        for (int r = 0; r < 4; r++) a[r] = As[(4 * tr + r) * 33 + kk];
#pragma unroll
        for (int c = 0; c < 4; c++) b[c] = Bs[(4 * tc + c) * 33 + kk];
#pragma unroll
        for (int r = 0; r < 4; r++)
#pragma unroll
            for (int c = 0; c < 4; c++) acc[r][c] += a[r] * b[c];
    }
#pragma unroll
    for (int r = 0; r < 4; r++)
#pragma unroll
        for (int c = 0; c < 4; c++)
            g_P1[k0 >> 5][(4 * tr + r) * 256 + n0 + 4 * tc + c] = acc[r][c];
}

template <int NP>
__device__ void ntk_body(const float* __restrict__ A, const float* __restrict__ Bm,
                         float* __restrict__ C, float* As, float* Bs,
                         int Ktot, int Kslice, int N, int n0, int koff, int tid) {
    int tr = tid >> 4, tc = tid & 15;
    float acc[4][4] = {};
    for (int k0 = koff; k0 < koff + Kslice; k0 += 32) {
#pragma unroll
        for (int i = 0; i < 8; i++) {
            int lin = tid + 256 * i, m = lin >> 5, k = lin & 31;
            float a = 0.f;
#pragma unroll
            for (int p = 0; p < NP; p++) a += A[(size_t)p * 64 * Ktot + m * Ktot + k0 + k];
            As[m * 33 + k] = a;
            Bs[m * 33 + k] = Bm[(n0 + m) * Ktot + k0 + k];
        }
        __syncthreads();
#pragma unroll 4
        for (int kk = 0; kk < 32; kk++) {
            float a[4], b[4];
#pragma unroll
            for (int r = 0; r < 4; r++) a[r] = As[(4 * tr + r) * 33 + kk];
#pragma unroll
            for (int c = 0; c < 4; c++) b[c] = Bs[(4 * tc + c) * 33 + kk];
#pragma unroll
            for (int r = 0; r < 4; r++)
#pragma unroll
                for (int c = 0; c < 4; c++) acc[r][c] += a[r] * b[c];
        }
        __syncthreads();
    }
#pragma unroll
    for (int r = 0; r < 4; r++)
#pragma unroll
        for (int c = 0; c < 4; c++)
            C[(4 * tr + r) * N + n0 + 4 * tc + c] = acc[r][c];
}

// software grid barrier over NB blocks (bar index i); counters reset at kernel end
__device__ __forceinline__ void gridbar(int i, int nb, int tid) {
    __syncthreads();
    if (tid == 0) {
        __threadfence();
        atomicAdd(&g_bar[i], 1);
        while (atomicAdd(&g_bar[i], 0) < nb) {}
        __threadfence();
    }
    __syncthreads();
}

// Whole weight fold in one kernel: 128 blocks, staged with grid barriers.
__global__ __launch_bounds__(256) void k_fold_all(const float* __restrict__ W4,
                                                  const float* __restrict__ W3,
                                                  const float* __restrict__ W2,
                                                  const float* __restrict__ W1) {
    __shared__ float As[64 * 33], Bs[64 * 33];
    int bid = blockIdx.x, tid = threadIdx.x;
    if (bid == 0 && tid < 64) g_doneB[tid] = 0;

    if (bid < 16)   // stage 1: P1 (4n x 4k)
        fold1_body(W4, W3, As, Bs, (bid & 3) * 64, (bid >> 2) * 32, tid);
    gridbar(0, 128, tid);

    if (bid < 64)   // stage 2: P2 (8n x 8k), Ktot=256, Kslice=32
        ntk_body<4>(&g_P1[0][0], W2, &g_P2[bid >> 3][0], As, Bs,
                    256, 32, 512, (bid & 7) * 64, (bid >> 3) * 32, tid);
    gridbar(1, 128, tid);

    // stage 3: P3 (16n x 8k), Ktot=512, Kslice=64
    ntk_body<8>(&g_P2[0][0], W1, &g_P3[bid >> 4][0], As, Bs,
                512, 64, 1024, (bid & 15) * 64, (bid >> 4) * 64, tid);
    gridbar(2, 128, tid);

    {   // cvt: one fp16 pair per thread (128*256 = 32768 pairs)
        int i = bid * 256 + tid;
        float w0 = 0.f, w1 = 0.f;
#pragma unroll
        for (int p = 0; p < 8; p++) {
            w0 += g_P3[p][2 * i];
            w1 += g_P3[p][2 * i + 1];
        }
        uint32_t hi, lo;
        hsplit2(w0, w1, hi, lo);
        g_WHi[i] = hi;
        g_WLo[i] = lo;
    }
    // final arrival; last block resets all barrier words (no one waits on bar 3)
    __syncthreads();
    if (tid == 0) {
        __threadfence();
        if (atomicAdd(&g_bar[3], 1) == 127) {
            g_bar[0] = 0; g_bar[1] = 0; g_bar[2] = 0; g_bar[3] = 0;
        }
    }
}

// tensor 64x64 step on fp16 hi/lo pairs: D = s*(A@B) + dg*I. out32: fp32 D.
__device__ __noinline__ void mm64t(unsigned char* sm, uint32_t sb, int oA, int oB, int oD,
                                   float s, float dg, int tid, int out32) {
    int w = tid >> 5, lane = tid & 31, g = lane >> 2, tq = lane & 3;
    int cr = (w & 3) * 16, cn = (w >> 2) * 32;
    int lr = lane & 15, ls = 8 * (lane >> 4);
    float acc[4][4] = {};
#pragma unroll
    for (int kk = 0; kk < 64; kk += 16) {
        uint32_t ah[4], al[4], bh[8], bl[8];
        uint32_t aa = sb + oA + (cr + lr) * 144 + (kk + ls) * 2;
        ldmA(ah, aa); ldmA(al, aa + 9216);
        uint32_t ba = sb + oB + (kk + lr) * 144 + (cn + ls) * 2;
        ldmBT(bh, ba); ldmBT(bh + 4, ba + 32);
        ldmBT(bl, ba + 9216); ldmBT(bl + 4, ba + 9216 + 32);
#pragma unroll
        for (int jb = 0; jb < 4; jb++) {
            int base = (jb >> 1) * 4 + (jb & 1) * 2;
            mma(acc[jb], ah, bh[base], bh[base + 1]);
            mma(acc[jb], ah, bl[base], bl[base + 1]);
            mma(acc[jb], al, bh[base], bh[base + 1]);
        }
    }
    if (out32) {
        float* Df = (float*)(sm + oD);
#pragma unroll
        for (int jb = 0; jb < 4; jb++) {
            int col = cn + 8 * jb + 2 * tq;
#pragma unroll
            for (int h2 = 0; h2 < 2; h2++) {
                int row = cr + g + 8 * h2;
                float v0 = s * acc[jb][2 * h2]     + ((row == col) ? dg : 0.f);
                float v1 = s * acc[jb][2 * h2 + 1] + ((row == col + 1) ? dg : 0.f);
                *(float2*)&Df[row * 64 + col] = make_float2(v0, v1);
            }
        }
    } else {
        __half* Dh = (__half*)(sm + oD);
        __half* Dl = (__half*)(sm + oD + 9216);
#pragma unroll
        for (int jb = 0; jb < 4; jb++) {
            int col = cn + 8 * jb + 2 * tq;
#pragma unroll
            for (int h2 = 0; h2 < 2; h2++) {
                int row = cr + g + 8 * h2;
                float v0 = s * acc[jb][2 * h2]     + ((row == col) ? dg : 0.f);
                float v1 = s * acc[jb][2 * h2 + 1] + ((row == col + 1) ? dg : 0.f);
                uint32_t hi, lo;
                hsplit2(v0, v1, hi, lo);
                *(uint32_t*)(Dh + row * 72 + col) = hi;
                *(uint32_t*)(Dl + row * 72 + col) = lo;
            }
        }
    }
    __syncthreads();
}

// Fused proj+cov (blocks 0..639, batch-major) and logm+linear (blocks 640..703,
// spinning on per-batch done counters). One launch; logm overlaps proj's tail.
__global__ __launch_bounds__(256, 2) void k_projlogm(const float* __restrict__ x,
                                                     const float* __restrict__ lw,
                                                     const float* __restrict__ lb,
                                                     float* __restrict__ out) {
    extern __shared__ __align__(16) unsigned char sm[];
    int tid = threadIdx.x, w = tid >> 5, lane = tid & 31;
    uint32_t sb = smem_u32(sm);

    if (blockIdx.x < 640) {
        const int OW0 = 0, OW1 = 18432, OX0 = 36864, OX1 = 54272;
        __shared__ float rs[2][64];
        int b = blockIdx.x / 10, tblk = blockIdx.x % 10, t0 = tblk * 128;
        const float* xb = x + (size_t)b * 1024 * 1200;
        int wr = (w >> 1) * 16, wc = (w & 1) * 64;
        int g = lane >> 2, tq = lane & 3;
        int arow = wr + (lane & 15), asel = 8 * (lane >> 4);
        int wm = tid >> 2, wq = 8 * (tid & 3);
        float acc[8][4] = {};

        for (int pc = 0; pc <= 16; pc++) {
            uint4 wh0, wh1, wl0, wl1;
            float4 xv[8];
            if (pc < 16) {
                const uint4* pH = (const uint4*)&g_WHi[wm * 512 + pc * 32 + wq];
                const uint4* pL = (const uint4*)&g_WLo[wm * 512 + pc * 32 + wq];
                wh0 = pH[0]; wh1 = pH[1]; wl0 = pL[0]; wl1 = pL[1];
#pragma unroll
                for (int i = 0; i < 8; i++) {
                    int lin = tid + 256 * i, k = lin >> 5, tt = t0 + 4 * (lin & 31);
                    xv[i] = (tt < 1200) ? *(const float4*)(xb + (size_t)(pc * 64 + k) * 1200 + tt)
                                        : make_float4(0.f, 0.f, 0.f, 0.f);
                }
            }
            if (pc > 0) {
                uint32_t wb = sb + (((pc - 1) & 1) ? OW1 : OW0);
                uint32_t xba = sb + (((pc - 1) & 1) ? OX1 : OX0);
#pragma unroll
                for (int ks = 0; ks < 4; ks++) {
                    int kk = 16 * ks;
                    uint32_t ah[4], al[4];
                    uint32_t aa = wb + arow * 144 + (kk + asel) * 2;
                    ldmA(ah, aa);
                    ldmA(al, aa + 9216);
#pragma unroll
                    for (int nb = 0; nb < 4; nb++) {
                        uint32_t r[4];
                        ldmBT(r, xba + (kk + (lane & 15)) * 272 + (wc + 16 * nb + asel) * 2);
                        mma(acc[2 * nb],     ah, r[0], r[1]);
                        mma(acc[2 * nb],     al, r[0], r[1]);
                        mma(acc[2 * nb + 1], ah, r[2], r[3]);
                        mma(acc[2 * nb + 1], al, r[2], r[3]);
                    }
                }
            }
            if (pc < 16) {
                unsigned char* dW = sm + ((pc & 1) ? OW1 : OW0) + wm * 144 + wq * 4;
                *(uint4*)dW = wh0; *(uint4*)(dW + 16) = wh1;
                *(uint4*)(dW + 9216) = wl0; *(uint4*)(dW + 9216 + 16) = wl1;
                unsigned char* dX = sm + ((pc & 1) ? OX1 : OX0);
#pragma unroll
                for (int i = 0; i < 8; i++) {
                    int lin = tid + 256 * i, k = lin >> 5, t4 = lin & 31;
                    uint2 p;
                    p.x = cvt2h(xv[i].x, xv[i].y);
                    p.y = cvt2h(xv[i].z, xv[i].w);
                    *(uint2*)(dX + k * 272 + 8 * t4) = p;
                }
            }
            __syncthreads();
        }
        {
            float s0 = 0.f, s1 = 0.f;
#pragma unroll
            for (int nf = 0; nf < 8; nf++) {
                s0 += acc[nf][0] + acc[nf][1];
                s1 += acc[nf][2] + acc[nf][3];
            }
            s0 += __shfl_xor_sync(0xffffffffu, s0, 1);
            s0 += __shfl_xor_sync(0xffffffffu, s0, 2);
            s1 += __shfl_xor_sync(0xffffffffu, s1, 1);
            s1 += __shfl_xor_sync(0xffffffffu, s1, 2);
            if (tq == 0) { rs[w & 1][wr + g] = s0; rs[w & 1][wr + g + 8] = s1; }
        }
        unsigned char* Yh = sm + OX0;
#pragma unroll
        for (int nf = 0; nf < 8; nf++) {
            int c0 = wc + 8 * nf + 2 * tq;
            *(uint32_t*)(Yh + (wr + g) * 272 + c0 * 2)     = cvt2h(acc[nf][0], acc[nf][1]);
            *(uint32_t*)(Yh + (wr + g + 8) * 272 + c0 * 2) = cvt2h(acc[nf][2], acc[nf][3]);
        }
        __syncthreads();
        if (tid < 64) g_rsumP[tblk][b * 64 + tid] = rs[0][tid] + rs[1][tid];
        {
            int cr = (w & 3) * 16, cn = (w >> 2) * 32;
            float cc[4][4] = {};
            uint32_t yh = sb + OX0;
#pragma unroll
            for (int kk = 0; kk < 128; kk += 16) {
                uint32_t ah[4], bh[8];
                ldmA(ah, yh + (cr + (lane & 15)) * 272 + (kk + asel) * 2);
                uint32_t ba = (cn + (lane & 15)) * 272 + (kk + asel) * 2;
                ldmA(bh, yh + ba); ldmA(bh + 4, yh + ba + 16 * 272);
#pragma unroll
                for (int jb = 0; jb < 4; jb++) {
                    int base = (jb >> 1) * 4 + (jb & 1);
                    mma(cc[jb], ah, bh[base], bh[base + 2]);
                }
            }
            float* Cp = g_Cpart[tblk][b];
#pragma unroll
            for (int jb = 0; jb < 4; jb++) {
                int col = cn + 8 * jb + 2 * tq;
                *(float2*)&Cp[(cr + g) * 64 + col]     = make_float2(cc[jb][0], cc[jb][1]);
                *(float2*)&Cp[(cr + g + 8) * 64 + col] = make_float2(cc[jb][2], cc[jb][3]);
            }
        }
        __syncthreads();
        if (tid == 0) {
            __threadfence();
            atomicAdd(&g_doneB[b], 1);
        }
        return;
    }

    // ---------------- logm + linear head ----------------
    int b = blockIdx.x - 640;
    __shared__ float s_r[64], red[64];
    __shared__ float s_inva, s_lna;
    const float iT = 1.f / 1200.f, iT1 = 1.f / 1199.f;

    if (tid == 0) {
        while (atomicAdd(&g_doneB[b], 0) < NTB) {}
        __threadfence();
    }
    __syncthreads();

    if (tid < 64) {
        float v = 0.f;
#pragma unroll
        for (int p = 0; p < NTB; p++) v += g_rsumP[p][b * 64 + tid];
        s_r[tid] = v;
    }
    __syncthreads();
    if (tid < 64) {
        float d = 0.f;
#pragma unroll
        for (int p = 0; p < NTB; p++) d += g_Cpart[p][b][tid * 65];
        red[tid] = (d - s_r[tid] * s_r[tid] * iT) * iT1;
    }
    __syncthreads();
    if (tid == 0) {
        float tr = 0.f;
        for (int i = 0; i < 64; i++) tr += red[i];
        float al = tr * (1.f / 64.f);
        s_inva = 1.f / al; s_lna = logf(al);
    }
    __syncthreads();
    float inva = s_inva;

    int oY = 0, oZ = 18432, oT = 36864, oU = 55296;
#pragma unroll
    for (int i = 0; i < 16; i++) {
        int lin = tid + 256 * i, r = lin >> 6, c = lin & 63;
        float v = 0.f;
#pragma unroll
        for (int p = 0; p < NTB; p++) v += g_Cpart[p][b][lin];
        float a = (v - s_r[r] * s_r[c] * iT) * iT1 * inva;
        __half h = __float2half(a);
        ((__half*)(sm + oY))[r * 72 + c] = h;
        ((__half*)(sm + oY + 9216))[r * 72 + c] = __float2half(a - __half2float(h));
        ((__half*)(sm + oZ))[r * 72 + c] = __float2half((r == c) ? 1.f : 0.f);
        ((__half*)(sm + oZ + 9216))[r * 72 + c] = __float2half(0.f);
    }
    __syncthreads();

    for (int it = 0; it < 5; it++) {
        mm64t(sm, sb, oZ, oY, oT, -1.f, 3.f, tid, 0);
        mm64t(sm, sb, oY, oT, oU, 0.5f, 0.f, tid, 0);
        mm64t(sm, sb, oT, oZ, oY, 0.5f, 0.f, tid, 0);
        int t = oY; oY = oU; oU = oT; oT = oZ; oZ = t;
    }
    __half *SH = (__half*)(sm + oY), *SL = (__half*)(sm + oY + 9216);
    __half *MH = (__half*)(sm + oZ), *ML = (__half*)(sm + oZ + 9216);
    __half *PH = (__half*)(sm + oT), *PL = (__half*)(sm + oT + 9216);
#pragma unroll
    for (int i = 0; i < 16; i++) {
        int lin = tid + 256 * i, r = lin >> 6, c = lin & 63;
        int idx = r * 72 + c;
        float m = __half2float(SH[idx]) + __half2float(SL[idx]) - ((r == c) ? 1.f : 0.f);
        __half mh = __float2half(m);
        MH[idx] = mh; ML[idx] = __float2half(m - __half2float(mh));
        float pv = (-1.f / 10.f) * m + ((r == c) ? (1.f / 9.f) : 0.f);
        __half ph = __float2half(pv);
        PH[idx] = ph; PL[idx] = __float2half(pv - __half2float(ph));
    }
    __syncthreads();
    int oP = oT, oQ = oU;
    for (int k = 8; k >= 1; k--) {
        float ck = ((k & 1) ? 1.f : -1.f) / (float)k;
        mm64t(sm, sb, oZ, oP, oQ, 1.f, ck, tid, 0);
        int t = oP; oP = oQ; oQ = t;
    }
    mm64t(sm, sb, oZ, oP, oQ, 2.f, s_lna, tid, 1);   // fp32 logC into oQ

    float* Qf = (float*)(sm + oQ);
    for (int j = w; j < 11; j += 8) {
        const float* wj = lw + (size_t)j * 4096;
        float s = 0.f;
        for (int i = lane * 4; i < 4096; i += 128) {
            float4 qv = *(float4*)&Qf[i];
            float4 wv = *(const float4*)&wj[i];
            s += qv.x * wv.x + qv.y * wv.y + qv.z * wv.z + qv.w * wv.w;
        }
#pragma unroll
        for (int o = 16; o > 0; o >>= 1) s += __shfl_xor_sync(0xffffffffu, s, o);
        if (lane == 0) out[b * 11 + j] = s + lb[j];
    }
}

extern "C" void kernel_launch(void* const* d_in, const int* in_sizes, int n_in,
                              void* d_out, int out_size) {
    const float* x  = (const float*)d_in[0];
    const float* W1 = (const float*)d_in[1];
    const float* W2 = (const float*)d_in[2];
    const float* W3 = (const float*)d_in[3];
    const float* W4 = (const float*)d_in[4];
    const float* lw = (const float*)d_in[5];
    const float* lb = (const float*)d_in[6];
    float* out = (float*)d_out;

    static bool done = false;
    if (!done) {
        cudaFuncSetAttribute(k_projlogm, cudaFuncAttributeMaxDynamicSharedMemorySize, 73728);
        done = true;
    }
    k_fold_all<<<128, 256>>>(W4, W3, W2, W1);          // whole weight fold, one launch
    k_projlogm<<<704, 256, 73728>>>(x, lw, lb, out);   // proj+cov, overlapped logm+head
}

// round 17
// speedup vs baseline: 1.8322x; 1.0440x over previous
#include <cuda_runtime.h>
#include <cuda_fp16.h>
#include <cstdint>

#define NTB 10
__device__ float g_P1[4][64 * 256];
__device__ float g_P2[8][64 * 512];
__device__ float g_P3[8][64 * 1024];
__device__ uint32_t g_WHi[64 * 512];
__device__ uint32_t g_WLo[64 * 512];
__device__ float g_Cpart[NTB][64][4096];
__device__ float g_rsumP[NTB][4096];
__device__ int g_doneB[64];
__device__ int g_bar[4];
__device__ int g_wReady;
__device__ int g_logmDone;

__device__ __forceinline__ uint32_t smem_u32(const void* p) {
    uint32_t a;
    asm("{ .reg .u64 t; cvta.to.shared.u64 t, %1; cvt.u32.u64 %0, t; }" : "=r"(a) : "l"(p));
    return a;
}
__device__ __forceinline__ int ldcg(const int* p) {
    int v;
    asm volatile("ld.global.cg.s32 %0, [%1];" : "=r"(v) : "l"(p));
    return v;
}
__device__ __forceinline__ uint32_t cvt2h(float lo, float hi) {
    uint32_t r;
    asm("cvt.rn.f16x2.f32 %0, %1, %2;" : "=r"(r) : "f"(hi), "f"(lo));
    return r;
}
__device__ __forceinline__ uint32_t hpack(__half a, __half b) {
    return (uint32_t)__half_as_ushort(a) | ((uint32_t)__half_as_ushort(b) << 16);
}
__device__ __forceinline__ void hsplit2(float v0, float v1, uint32_t& hi, uint32_t& lo) {
    __half h0 = __float2half(v0), h1 = __float2half(v1);
    hi = hpack(h0, h1);
    lo = hpack(__float2half(v0 - __half2float(h0)), __float2half(v1 - __half2float(h1)));
}
__device__ __forceinline__ void ldmA(uint32_t* r, uint32_t a) {
    asm volatile("ldmatrix.sync.aligned.m8n8.x4.shared.b16 {%0,%1,%2,%3}, [%4];"
                 : "=r"(r[0]), "=r"(r[1]), "=r"(r[2]), "=r"(r[3]) : "r"(a));
}
__device__ __forceinline__ void ldmBT(uint32_t* r, uint32_t a) {
    asm volatile("ldmatrix.sync.aligned.m8n8.x4.trans.shared.b16 {%0,%1,%2,%3}, [%4];"
                 : "=r"(r[0]), "=r"(r[1]), "=r"(r[2]), "=r"(r[3]) : "r"(a));
}
__device__ __forceinline__ void mma(float* c, const uint32_t a[4], uint32_t b0, uint32_t b1) {
    asm volatile("mma.sync.aligned.m16n8k16.row.col.f32.f16.f16.f32 "
                 "{%0,%1,%2,%3},{%4,%5,%6,%7},{%8,%9},{%0,%1,%2,%3};"
                 : "+f"(c[0]), "+f"(c[1]), "+f"(c[2]), "+f"(c[3])
                 : "r"(a[0]), "r"(a[1]), "r"(a[2]), "r"(a[3]), "r"(b0), "r"(b1));
}

// ---- fold bodies ----
__device__ void fold1_body(const float* __restrict__ W4, const float* __restrict__ W3,
                           float* As, float* Bs, int n0, int k0, int tid) {
    int tr = tid >> 4, tc = tid & 15;
    float acc[4][4] = {};
#pragma unroll
    for (int i = 0; i < 8; i++) {
        int lin = tid + 256 * i, m = lin >> 5, k = lin & 31;
        As[m * 33 + k] = W4[(k0 + k) * 64 + m];
        Bs[m * 33 + k] = W3[(n0 + m) * 128 + k0 + k];
    }
    __syncthreads();
#pragma unroll 4
    for (int kk = 0; kk < 32; kk++) {
        float a[4], b[4];
#pragma unroll
        for (int r = 0; r < 4; r++) a[r] = As[(4 * tr + r) * 33 + kk];
#pragma unroll
        for (int c = 0; c < 4; c++) b[c] = Bs[(4 * tc + c) * 33 + kk];
#pragma unroll
        for (int r = 0; r < 4; r++)
#pragma unroll
            for (int c = 0; c < 4; c++) acc[r][c] += a[r] * b[c];
    }
#pragma unroll
    for (int r = 0; r < 4; r++)
#pragma unroll
        for (int c = 0; c < 4; c++)
            g_P1[k0 >> 5][(4 * tr + r) * 256 + n0 + 4 * tc + c] = acc[r][c];
}

template <int NP>
__device__ void ntk_body(const float* __restrict__ A, const float* __restrict__ Bm,
                         float* __restrict__ C, float* As, float* Bs,
                         int Ktot, int Kslice, int N, int n0, int koff, int tid) {
    int tr = tid >> 4, tc = tid & 15;
    float acc[4][4] = {};
    for (int k0 = koff; k0 < koff + Kslice; k0 += 32) {
#pragma unroll
        for (int i = 0; i < 8; i++) {
            int lin = tid + 256 * i, m = lin >> 5, k = lin & 31;
            float a = 0.f;
#pragma unroll
            for (int p = 0; p < NP; p++) a += A[(size_t)p * 64 * Ktot + m * Ktot + k0 + k];
            As[m * 33 + k] = a;
            Bs[m * 33 + k] = Bm[(n0 + m) * Ktot + k0 + k];
        }
        __syncthreads();
#pragma unroll 4
        for (int kk = 0; kk < 32; kk++) {
            float a[4], b[4];
#pragma unroll
            for (int r = 0; r < 4; r++) a[r] = As[(4 * tr + r) * 33 + kk];
#pragma unroll
            for (int c = 0; c < 4; c++) b[c] = Bs[(4 * tc + c) * 33 + kk];
#pragma unroll
            for (int r = 0; r < 4; r++)
#pragma unroll
                for (int c = 0; c < 4; c++) acc[r][c] += a[r] * b[c];
        }
        __syncthreads();
    }
#pragma unroll
    for (int r = 0; r < 4; r++)
#pragma unroll
        for (int c = 0; c < 4; c++)
            C[(4 * tr + r) * N + n0 + 4 * tc + c] = acc[r][c];
}

// grid barrier over 128 fold blocks; poll with ld.cg (no atomic contention)
__device__ __forceinline__ void gridbar(int i, int tid) {
    __syncthreads();
    if (tid == 0) {
        __threadfence();
        atomicAdd(&g_bar[i], 1);
        while (ldcg(&g_bar[i]) < 128) __nanosleep(32);
        __threadfence();
    }
    __syncthreads();
}

// tensor 64x64 step on fp16 hi/lo pairs: D = s*(A@B) + dg*I. out32: fp32 D.
__device__ __noinline__ void mm64t(unsigned char* sm, uint32_t sb, int oA, int oB, int oD,
                                   float s, float dg, int tid, int out32) {
    int w = tid >> 5, lane = tid & 31, g = lane >> 2, tq = lane & 3;
    int cr = (w & 3) * 16, cn = (w >> 2) * 32;
    int lr = lane & 15, ls = 8 * (lane >> 4);
    float acc[4][4] = {};
#pragma unroll
    for (int kk = 0; kk < 64; kk += 16) {
        uint32_t ah[4], al[4], bh[8], bl[8];
        uint32_t aa = sb + oA + (cr + lr) * 144 + (kk + ls) * 2;
        ldmA(ah, aa); ldmA(al, aa + 9216);
        uint32_t ba = sb + oB + (kk + lr) * 144 + (cn + ls) * 2;
        ldmBT(bh, ba); ldmBT(bh + 4, ba + 32);
        ldmBT(bl, ba + 9216); ldmBT(bl + 4, ba + 9216 + 32);
#pragma unroll
        for (int jb = 0; jb < 4; jb++) {
            int base = (jb >> 1) * 4 + (jb & 1) * 2;
            mma(acc[jb], ah, bh[base], bh[base + 1]);
            mma(acc[jb], ah, bl[base], bl[base + 1]);
            mma(acc[jb], al, bh[base], bh[base + 1]);
        }
    }
    if (out32) {
        float* Df = (float*)(sm + oD);
#pragma unroll
        for (int jb = 0; jb < 4; jb++) {
            int col = cn + 8 * jb + 2 * tq;
#pragma unroll
            for (int h2 = 0; h2 < 2; h2++) {
                int row = cr + g + 8 * h2;
                float v0 = s * acc[jb][2 * h2]     + ((row == col) ? dg : 0.f);
                float v1 = s * acc[jb][2 * h2 + 1] + ((row == col + 1) ? dg : 0.f);
                *(float2*)&Df[row * 64 + col] = make_float2(v0, v1);
            }
        }
    } else {
        __half* Dh = (__half*)(sm + oD);
        __half* Dl = (__half*)(sm + oD + 9216);
#pragma unroll
        for (int jb = 0; jb < 4; jb++) {
            int col = cn + 8 * jb + 2 * tq;
#pragma unroll
            for (int h2 = 0; h2 < 2; h2++) {
                int row = cr + g + 8 * h2;
                float v0 = s * acc[jb][2 * h2]     + ((row == col) ? dg : 0.f);
                float v1 = s * acc[jb][2 * h2 + 1] + ((row == col + 1) ? dg : 0.f);
                uint32_t hi, lo;
                hsplit2(v0, v1, hi, lo);
                *(uint32_t*)(Dh + row * 72 + col) = hi;
                *(uint32_t*)(Dl + row * 72 + col) = lo;
            }
        }
    }
    __syncthreads();
}

// ONE kernel: fold (blocks 0..127) -> proj+cov (blocks 0..639) -> logm (640..703)
__global__ __launch_bounds__(256, 2) void k_all(const float* __restrict__ x,
                                                const float* __restrict__ W4,
                                                const float* __restrict__ W3,
                                                const float* __restrict__ W2,
                                                const float* __restrict__ W1,
                                                const float* __restrict__ lw,
                                                const float* __restrict__ lb,
                                                float* __restrict__ out) {
    extern __shared__ __align__(16) unsigned char sm[];
    int bid = blockIdx.x, tid = threadIdx.x, w = tid >> 5, lane = tid & 31;
    uint32_t sb = smem_u32(sm);

    if (bid < 640) {
        if (bid < 128) {
            // ---------------- weight fold ----------------
            float* As = (float*)sm;
            float* Bs = As + 64 * 33;
            if (bid < 16)
                fold1_body(W4, W3, As, Bs, (bid & 3) * 64, (bid >> 2) * 32, tid);
            gridbar(0, tid);
            if (bid < 64)
                ntk_body<4>(&g_P1[0][0], W2, &g_P2[bid >> 3][0], As, Bs,
                            256, 32, 512, (bid & 7) * 64, (bid >> 3) * 32, tid);
            gridbar(1, tid);
            ntk_body<8>(&g_P2[0][0], W1, &g_P3[bid >> 4][0], As, Bs,
                        512, 64, 1024, (bid & 15) * 64, (bid >> 4) * 64, tid);
            gridbar(2, tid);
            {   // cvt: one fp16 pair per thread
                int i = bid * 256 + tid;
                float w0 = 0.f, w1 = 0.f;
#pragma unroll
                for (int p = 0; p < 8; p++) {
                    w0 += g_P3[p][2 * i];
                    w1 += g_P3[p][2 * i + 1];
                }
                uint32_t hi, lo;
                hsplit2(w0, w1, hi, lo);
                g_WHi[i] = hi;
                g_WLo[i] = lo;
            }
            __syncthreads();
            if (tid == 0) {
                __threadfence();
                if (atomicAdd(&g_bar[3], 1) == 127) atomicExch(&g_wReady, 1);
            }
        }
        // all proj blocks wait for W
        if (tid == 0) {
            while (ldcg(&g_wReady) == 0) __nanosleep(64);
            __threadfence();
        }
        __syncthreads();

        // ---------------- projection + cov partials ----------------
        const int OW0 = 0, OW1 = 18432, OX0 = 36864, OX1 = 54272;
        __shared__ float rs[2][64];
        int b = bid / 10, tblk = bid % 10, t0 = tblk * 128;
        const float* xb = x + (size_t)b * 1024 * 1200;
        int wr = (w >> 1) * 16, wc = (w & 1) * 64;
        int g = lane >> 2, tq = lane & 3;
        int arow = wr + (lane & 15), asel = 8 * (lane >> 4);
        int wm = tid >> 2, wq = 8 * (tid & 3);
        float acc[8][4] = {};

        for (int pc = 0; pc <= 16; pc++) {
            uint4 wh0, wh1, wl0, wl1;
            float4 xv[8];
            if (pc < 16) {
                const uint4* pH = (const uint4*)&g_WHi[wm * 512 + pc * 32 + wq];
                const uint4* pL = (const uint4*)&g_WLo[wm * 512 + pc * 32 + wq];
                wh0 = pH[0]; wh1 = pH[1]; wl0 = pL[0]; wl1 = pL[1];
#pragma unroll
                for (int i = 0; i < 8; i++) {
                    int lin = tid + 256 * i, k = lin >> 5, tt = t0 + 4 * (lin & 31);
                    xv[i] = (tt < 1200) ? *(const float4*)(xb + (size_t)(pc * 64 + k) * 1200 + tt)
                                        : make_float4(0.f, 0.f, 0.f, 0.f);
                }
            }
            if (pc > 0) {
                uint32_t wb = sb + (((pc - 1) & 1) ? OW1 : OW0);
                uint32_t xba = sb + (((pc - 1) & 1) ? OX1 : OX0);
#pragma unroll
                for (int ks = 0; ks < 4; ks++) {
                    int kk = 16 * ks;
                    uint32_t ah[4], al[4];
                    uint32_t aa = wb + arow * 144 + (kk + asel) * 2;
                    ldmA(ah, aa);
                    ldmA(al, aa + 9216);
#pragma unroll
                    for (int nb = 0; nb < 4; nb++) {
                        uint32_t r[4];
                        ldmBT(r, xba + (kk + (lane & 15)) * 272 + (wc + 16 * nb + asel) * 2);
                        mma(acc[2 * nb],     ah, r[0], r[1]);
                        mma(acc[2 * nb],     al, r[0], r[1]);
                        mma(acc[2 * nb + 1], ah, r[2], r[3]);
                        mma(acc[2 * nb + 1], al, r[2], r[3]);
                    }
                }
            }
            if (pc < 16) {
                unsigned char* dW = sm + ((pc & 1) ? OW1 : OW0) + wm * 144 + wq * 4;
                *(uint4*)dW = wh0; *(uint4*)(dW + 16) = wh1;
                *(uint4*)(dW + 9216) = wl0; *(uint4*)(dW + 9216 + 16) = wl1;
                unsigned char* dX = sm + ((pc & 1) ? OX1 : OX0);
#pragma unroll
                for (int i = 0; i < 8; i++) {
                    int lin = tid + 256 * i, k = lin >> 5, t4 = lin & 31;
                    uint2 p;
                    p.x = cvt2h(xv[i].x, xv[i].y);
                    p.y = cvt2h(xv[i].z, xv[i].w);
                    *(uint2*)(dX + k * 272 + 8 * t4) = p;
                }
            }
            __syncthreads();
        }
        {
            float s0 = 0.f, s1 = 0.f;
#pragma unroll
            for (int nf = 0; nf < 8; nf++) {
                s0 += acc[nf][0] + acc[nf][1];
                s1 += acc[nf][2] + acc[nf][3];
            }
            s0 += __shfl_xor_sync(0xffffffffu, s0, 1);
            s0 += __shfl_xor_sync(0xffffffffu, s0, 2);
            s1 += __shfl_xor_sync(0xffffffffu, s1, 1);
            s1 += __shfl_xor_sync(0xffffffffu, s1, 2);
            if (tq == 0) { rs[w & 1][wr + g] = s0; rs[w & 1][wr + g + 8] = s1; }
        }
        unsigned char* Yh = sm + OX0;
#pragma unroll
        for (int nf = 0; nf < 8; nf++) {
            int c0 = wc + 8 * nf + 2 * tq;
            *(uint32_t*)(Yh + (wr + g) * 272 + c0 * 2)     = cvt2h(acc[nf][0], acc[nf][1]);
            *(uint32_t*)(Yh + (wr + g + 8) * 272 + c0 * 2) = cvt2h(acc[nf][2], acc[nf][3]);
        }
        __syncthreads();
        if (tid < 64) g_rsumP[tblk][b * 64 + tid] = rs[0][tid] + rs[1][tid];
        {
            int cr = (w & 3) * 16, cn = (w >> 2) * 32;
            float cc[4][4] = {};
            uint32_t yh = sb + OX0;
#pragma unroll
            for (int kk = 0; kk < 128; kk += 16) {
                uint32_t ah[4], bh[8];
                ldmA(ah, yh + (cr + (lane & 15)) * 272 + (kk + asel) * 2);
                uint32_t ba = (cn + (lane & 15)) * 272 + (kk + asel) * 2;
                ldmA(bh, yh + ba); ldmA(bh + 4, yh + ba + 16 * 272);
#pragma unroll
                for (int jb = 0; jb < 4; jb++) {
                    int base = (jb >> 1) * 4 + (jb & 1);
                    mma(cc[jb], ah, bh[base], bh[base + 2]);
                }
            }
            float* Cp = g_Cpart[tblk][b];
#pragma unroll
            for (int jb = 0; jb < 4; jb++) {
                int col = cn + 8 * jb + 2 * tq;
                *(float2*)&Cp[(cr + g) * 64 + col]     = make_float2(cc[jb][0], cc[jb][1]);
                *(float2*)&Cp[(cr + g + 8) * 64 + col] = make_float2(cc[jb][2], cc[jb][3]);
            }
        }
        __syncthreads();
        if (tid == 0) {
            __threadfence();
            atomicAdd(&g_doneB[b], 1);
        }
        return;
    }

    // ---------------- logm + linear head ----------------
    int b = bid - 640;
    __shared__ float s_r[64], red[64];
    __shared__ float s_inva, s_lna;
    const float iT = 1.f / 1200.f, iT1 = 1.f / 1199.f;

    if (tid == 0) {
        while (ldcg(&g_doneB[b]) < NTB) __nanosleep(64);
        __threadfence();
    }
    __syncthreads();

    if (tid < 64) {
        float v = 0.f;
#pragma unroll
        for (int p = 0; p < NTB; p++) v += g_rsumP[p][b * 64 + tid];
        s_r[tid] = v;
    }
    __syncthreads();
    if (tid < 64) {
        float d = 0.f;
#pragma unroll
        for (int p = 0; p < NTB; p++) d += g_Cpart[p][b][tid * 65];
        red[tid] = (d - s_r[tid] * s_r[tid] * iT) * iT1;
    }
    __syncthreads();
    if (tid == 0) {
        float tr = 0.f;
        for (int i = 0; i < 64; i++) tr += red[i];
        float al = tr * (1.f / 64.f);
        s_inva = 1.f / al; s_lna = logf(al);
    }
    __syncthreads();
    float inva = s_inva;

    int oY = 0, oZ = 18432, oT = 36864, oU = 55296;
#pragma unroll
    for (int i = 0; i < 16; i++) {
        int lin = tid + 256 * i, r = lin >> 6, c = lin & 63;
        float v = 0.f;
#pragma unroll
        for (int p = 0; p < NTB; p++) v += g_Cpart[p][b][lin];
        float a = (v - s_r[r] * s_r[c] * iT) * iT1 * inva;
        __half h = __float2half(a);
        ((__half*)(sm + oY))[r * 72 + c] = h;
        ((__half*)(sm + oY + 9216))[r * 72 + c] = __float2half(a - __half2float(h));
        ((__half*)(sm + oZ))[r * 72 + c] = __float2half((r == c) ? 1.f : 0.f);
        ((__half*)(sm + oZ + 9216))[r * 72 + c] = __float2half(0.f);
    }
    __syncthreads();

    for (int it = 0; it < 5; it++) {
        mm64t(sm, sb, oZ, oY, oT, -1.f, 3.f, tid, 0);
        mm64t(sm, sb, oY, oT, oU, 0.5f, 0.f, tid, 0);
        mm64t(sm, sb, oT, oZ, oY, 0.5f, 0.f, tid, 0);
        int t = oY; oY = oU; oU = oT; oT = oZ; oZ = t;
    }
    __half *SH = (__half*)(sm + oY), *SL = (__half*)(sm + oY + 9216);
    __half *MH = (__half*)(sm + oZ), *ML = (__half*)(sm + oZ + 9216);
    __half *PH = (__half*)(sm + oT), *PL = (__half*)(sm + oT + 9216);
#pragma unroll
    for (int i = 0; i < 16; i++) {
        int lin = tid + 256 * i, r = lin >> 6, c = lin & 63;
        int idx = r * 72 + c;
        float m = __half2float(SH[idx]) + __half2float(SL[idx]) - ((r == c) ? 1.f : 0.f);
        __half mh = __float2half(m);
        MH[idx] = mh; ML[idx] = __float2half(m - __half2float(mh));
        float pv = (-1.f / 10.f) * m + ((r == c) ? (1.f / 9.f) : 0.f);
        __half ph = __float2half(pv);
        PH[idx] = ph; PL[idx] = __float2half(pv - __half2float(ph));
    }
    __syncthreads();
    int oP = oT, oQ = oU;
    for (int k = 8; k >= 1; k--) {
        float ck = ((k & 1) ? 1.f : -1.f) / (float)k;
        mm64t(sm, sb, oZ, oP, oQ, 1.f, ck, tid, 0);
        int t = oP; oP = oQ; oQ = t;
    }
    mm64t(sm, sb, oZ, oP, oQ, 2.f, s_lna, tid, 1);   // fp32 logC into oQ

    float* Qf = (float*)(sm + oQ);
    for (int j = w; j < 11; j += 8) {
        const float* wj = lw + (size_t)j * 4096;
        float s = 0.f;
        for (int i = lane * 4; i < 4096; i += 128) {
            float4 qv = *(float4*)&Qf[i];
            float4 wv = *(const float4*)&wj[i];
            s += qv.x * wv.x + qv.y * wv.y + qv.z * wv.z + qv.w * wv.w;
        }
#pragma unroll
        for (int o = 16; o > 0; o >>= 1) s += __shfl_xor_sync(0xffffffffu, s, o);
        if (lane == 0) out[b * 11 + j] = s + lb[j];
    }

    // last logm block resets all coordination state (ordered after all consumers)
    __syncthreads();
    if (tid == 0) {
        __threadfence();
        if (atomicAdd(&g_logmDone, 1) == 63) {
            g_bar[0] = 0; g_bar[1] = 0; g_bar[2] = 0; g_bar[3] = 0;
            atomicExch(&g_wReady, 0);
            for (int i = 0; i < 64; i++) g_doneB[i] = 0;
            g_logmDone = 0;
            __threadfence();
        }
    }
}

extern "C" void kernel_launch(void* const* d_in, const int* in_sizes, int n_in,
                              void* d_out, int out_size) {
    const float* x  = (const float*)d_in[0];
    const float* W1 = (const float*)d_in[1];
    const float* W2 = (const float*)d_in[2];
    const float* W3 = (const float*)d_in[3];
    const float* W4 = (const float*)d_in[4];
    const float* lw = (const float*)d_in[5];
    const float* lb = (const float*)d_in[6];
    float* out = (float*)d_out;

    static bool done = false;
    if (!done) {
        cudaFuncSetAttribute(k_all, cudaFuncAttributeMaxDynamicSharedMemorySize, 73728);
        done = true;
    }
    k_all<<<704, 256, 73728>>>(x, W4, W3, W2, W1, lw, lb, out);
}